// round 14
// baseline (speedup 1.0000x reference)
#include <cuda_runtime.h>
#include <cuda_fp16.h>
#include <math.h>

#define NDT 30000
#define NOD 10000
#define WSLOT 16384
#define TILE 1024

static inline int cdiv(long long a, long long b) { return (int)((a + b - 1) / b); }

// ---------------- fp16 mma / ldmatrix helpers -----------------------------------
#define MMA_F16(d, a, b0, b1)                                              \
    asm volatile("mma.sync.aligned.m16n8k16.row.col.f32.f16.f16.f32 "      \
                 "{%0,%1,%2,%3}, {%4,%5,%6,%7}, {%8,%9}, {%0,%1,%2,%3};"   \
                 : "+f"((d)[0]), "+f"((d)[1]), "+f"((d)[2]), "+f"((d)[3])  \
                 : "r"((a)[0]), "r"((a)[1]), "r"((a)[2]), "r"((a)[3]),     \
                   "r"(b0), "r"(b1))

#define LDSM_X4(r0, r1, r2, r3, addr)                                      \
    asm volatile("ldmatrix.sync.aligned.m8n8.x4.shared.b16 "               \
                 "{%0,%1,%2,%3}, [%4];"                                    \
                 : "=r"(r0), "=r"(r1), "=r"(r2), "=r"(r3) : "r"(addr))

__device__ __forceinline__ unsigned smem_u32(const void* p) {
    return (unsigned)__cvta_generic_to_shared(p);
}

// ---------------- device scratch ------------------------------------------------
__device__ __half g_xdth[NDT * 128];
__device__ __half g_xodh[NOD * 64];
__device__ __half g_acc1[NDT * 128];
__device__ __half g_acc2[NOD * 128];
__device__ __half g_acc3[NDT * 128];
__device__ __half g_h [NDT * 128];
__device__ __half g_d1[NDT * 128];
__device__ __half g_od2[NOD * 128];
__device__ __half g_zodh[NOD * 64];
__device__ __half g_zdth[NDT * 64];
__device__ __half g_wh[13 * WSLOT];
// CSR scratch
__device__ int g_deg1[NDT];
__device__ int g_rp1[NDT + 1];
__device__ int g_fill1[NDT];
__device__ int g_es1[500000];
__device__ int g_deg2[NOD];
__device__ int g_rp2[NOD + 1];
__device__ int g_fill2[NOD];
__device__ int g_es2[300000];
__device__ int g_part1[64];
__device__ int g_part2[64];
__device__ int g_scan_cnt;

// ---------------- fused prep: weight transpose + input convert + zeroing --------
struct WTList {
    const float* src[13];
    int K[13];
    int N[13];
};
__global__ void k_prep(WTList L, __half* __restrict__ wdst, int wt_tot,
                       const float* __restrict__ x_dt, __half* __restrict__ xdh,
                       const float* __restrict__ x_od, __half* __restrict__ xoh,
                       int* __restrict__ deg1, int* __restrict__ deg2,
                       int* __restrict__ cnt) {
    int i = blockIdx.x * blockDim.x + threadIdx.x;
    if (i < wt_tot) {
        int s = 0, off = i;
        while (off >= L.K[s] * L.N[s]) { off -= L.K[s] * L.N[s]; s++; }
        int K = L.K[s];
        int n = off / K, k = off - n * K;
        wdst[(size_t)s * WSLOT + off] = __float2half(L.src[s][k * L.N[s] + n]);
        return;
    }
    i -= wt_tot;
    const int n1 = NDT * 128 / 4, n2 = NOD * 64 / 4;
    const int z1 = NDT / 4, z2 = NOD / 4;
    if (i < n1) {
        float4 v = *(const float4*)(x_dt + i * 4);
        __half2 h0 = __floats2half2_rn(v.x, v.y);
        __half2 h1 = __floats2half2_rn(v.z, v.w);
        *(uint2*)(xdh + i * 4) = make_uint2(*(unsigned*)&h0, *(unsigned*)&h1);
    } else if (i < n1 + n2) {
        int j = i - n1;
        float4 v = *(const float4*)(x_od + j * 4);
        __half2 h0 = __floats2half2_rn(v.x, v.y);
        __half2 h1 = __floats2half2_rn(v.z, v.w);
        *(uint2*)(xoh + j * 4) = make_uint2(*(unsigned*)&h0, *(unsigned*)&h1);
    } else if (i < n1 + n2 + z1) {
        ((int4*)deg1)[i - (n1 + n2)] = make_int4(0, 0, 0, 0);
    } else if (i < n1 + n2 + z1 + z2) {
        ((int4*)deg2)[i - (n1 + n2 + z1)] = make_int4(0, 0, 0, 0);
    } else if (i == n1 + n2 + z1 + z2) {
        *cnt = 0;
    }
}

// ---------------- CSR build: 4 edges/thread for MLP -----------------------------
__global__ void k_degree2(const int* __restrict__ c1, int E1, int* __restrict__ deg1,
                          const int* __restrict__ rdst, int E2, int* __restrict__ deg2) {
    int i4 = (blockIdx.x * blockDim.x + threadIdx.x) * 4;
#pragma unroll
    for (int j = 0; j < 4; j++) {
        int i = i4 + j;
        if (i < E1) atomicAdd(deg1 + __ldg(c1 + i), 1);
        else if (i < E1 + E2) atomicAdd(deg2 + __ldg(rdst + (i - E1)), 1);
    }
}

// fused two-phase scan with device-wide spin barrier (40 blocks, all resident).
// fill[i] initialized to rp[i] so reorder atomicAdds it directly.
__global__ void k_scan(const int* __restrict__ deg1, int n1, int* __restrict__ rp1,
                       int* __restrict__ fill1, int* __restrict__ part1, int tiles1,
                       const int* __restrict__ deg2, int n2, int* __restrict__ rp2,
                       int* __restrict__ fill2, int* __restrict__ part2, int tiles2,
                       int* __restrict__ cnt) {
    int b = blockIdx.x;
    const int* deg; int n; int* rp; int* fill; int* part; int tt, tiles;
    if (b < tiles1) { deg = deg1; n = n1; rp = rp1; fill = fill1; part = part1; tt = b; tiles = tiles1; }
    else { deg = deg2; n = n2; rp = rp2; fill = fill2; part = part2; tt = b - tiles1; tiles = tiles2; }
    __shared__ int wsum[8];
    __shared__ int s_off;
    int t = threadIdx.x, lane = t & 31, w = t >> 5;
    int base = tt * TILE + t * 4;
    int d[4]; int tot = 0;
#pragma unroll
    for (int j = 0; j < 4; j++) { d[j] = (base + j < n) ? deg[base + j] : 0; tot += d[j]; }
    int inc = tot;
#pragma unroll
    for (int o = 1; o < 32; o <<= 1) {
        int u = __shfl_up_sync(0xffffffffu, inc, o);
        if (lane >= o) inc += u;
    }
    if (lane == 31) wsum[w] = inc;
    __syncthreads();
    if (t == 0) {
        int s = 0;
#pragma unroll
        for (int j = 0; j < 8; j++) s += wsum[j];
        part[tt] = s;
        __threadfence();
        atomicAdd(cnt, 1);
        while (atomicAdd(cnt, 0) < tiles1 + tiles2) {}
        __threadfence();
    }
    __syncthreads();
    if (t < 32) {
        int v = (t < tt) ? atomicAdd(part + t, 0) : 0;
#pragma unroll
        for (int o = 16; o; o >>= 1) v += __shfl_xor_sync(0xffffffffu, v, o);
        if (t == 0) s_off = v;
    }
    __syncthreads();
    int woff = 0;
#pragma unroll
    for (int j = 0; j < 8; j++) if (j < w) woff += wsum[j];
    int run = s_off + woff + inc - tot;
#pragma unroll
    for (int j = 0; j < 4; j++) {
        if (base + j < n) { rp[base + j] = run; fill[base + j] = run; run += d[j]; }
    }
    if (tt == tiles - 1 && t == blockDim.x - 1) rp[n] = run;
}

// direct-offset reorder, 4 independent edges per thread (latency hiding).
__global__ void k_reorder2(const int* __restrict__ s1, const int* __restrict__ t1, int E1,
                           int* __restrict__ f1, int* __restrict__ e1,
                           const int* __restrict__ s2, const int* __restrict__ t2, int E2,
                           int* __restrict__ f2, int* __restrict__ e2) {
    int i4 = (blockIdx.x * blockDim.x + threadIdx.x) * 4;
    int d[4], pos[4];
#pragma unroll
    for (int j = 0; j < 4; j++) {
        int i = i4 + j;
        d[j] = -1;
        if (i < E1) d[j] = __ldg(t1 + i);
        else if (i < E1 + E2) d[j] = __ldg(t2 + (i - E1));
    }
#pragma unroll
    for (int j = 0; j < 4; j++) {
        int i = i4 + j;
        if (d[j] >= 0) {
            if (i < E1) pos[j] = atomicAdd(f1 + d[j], 1);
            else        pos[j] = atomicAdd(f2 + d[j], 1);
        }
    }
#pragma unroll
    for (int j = 0; j < 4; j++) {
        int i = i4 + j;
        if (d[j] >= 0) {
            if (i < E1) e1[pos[j]] = __ldg(s1 + i);
            else        e2[pos[j]] = __ldg(s2 + (i - E1));
        }
    }
}

// ---------------- mean aggregation: warp per dst, 4 edges in flight -------------
__global__ __launch_bounds__(256)
void k_aggh2(const __half* __restrict__ X1, const int* __restrict__ es1,
             const int* __restrict__ rp1, __half* __restrict__ acc1, int n1,
             const __half* __restrict__ X2, const int* __restrict__ es2,
             const int* __restrict__ rp2, __half* __restrict__ acc2, int n2) {
    int w = (blockIdx.x * blockDim.x + threadIdx.x) >> 5;
    const __half* X; const int* es; const int* rowptr; __half* acc;
    if (w < n1) { X = X1; es = es1; rowptr = rp1; acc = acc1; }
    else if (w < n1 + n2) { X = X2; es = es2; rowptr = rp2; acc = acc2; w -= n1; }
    else return;
    int lane = threadIdx.x & 31;
    int grp4 = lane >> 3;
    int sub = lane & 7;
    int beg = __ldg(rowptr + w);
    int end = __ldg(rowptr + w + 1);
    float s[16];
#pragma unroll
    for (int k = 0; k < 16; k++) s[k] = 0.f;
    for (int base = beg; base < end; base += 32) {
        int p = 0;
        if (base + lane < end) p = __ldg(es + base + lane);
        int cnt = min(32, end - base);
        for (int j = 0; j < cnt; j += 4) {
            int e = j + grp4;
            int sr = __shfl_sync(0xffffffffu, p, e);
            if (e < cnt) {
                const uint4* row = (const uint4*)(X + (size_t)sr * 128 + sub * 16);
                uint4 v0 = __ldg(row);
                uint4 v1 = __ldg(row + 1);
                unsigned vv[8] = {v0.x, v0.y, v0.z, v0.w, v1.x, v1.y, v1.z, v1.w};
#pragma unroll
                for (int k = 0; k < 8; k++) {
                    float2 f = __half22float2(*(__half2*)&vv[k]);
                    s[2 * k] += f.x;
                    s[2 * k + 1] += f.y;
                }
            }
        }
    }
#pragma unroll
    for (int k = 0; k < 16; k++) {
        s[k] += __shfl_xor_sync(0xffffffffu, s[k], 8);
        s[k] += __shfl_xor_sync(0xffffffffu, s[k], 16);
    }
    if (grp4 == 0) {
        float inv = 1.f / fmaxf((float)(end - beg), 1.f);
        unsigned o[8];
#pragma unroll
        for (int k = 0; k < 8; k++) {
            __half2 hv = __floats2half2_rn(s[2 * k] * inv, s[2 * k + 1] * inv);
            o[k] = *(unsigned*)&hv;
        }
        uint4* dst = (uint4*)(acc + (size_t)w * 128 + sub * 16);
        dst[0] = make_uint4(o[0], o[1], o[2], o[3]);
        dst[1] = make_uint4(o[4], o[5], o[6], o[7]);
    }
}

// ---------------- generic 2-problem fp16 GEMM (256 thr, 2m x 4n warps) ----------
struct GemmProb {
    const __half* A; int K1;
    const __half* B; int K2;
    const __half* W1; const __half* W2;   // pre-transposed [N][K] f16
    const float* bias;
    __half* Y;
    int M;
    int relu;
};

template <int NCOLS, int BR>
__global__ __launch_bounds__(256, 2)
void gemm_h(GemmProb p0, GemmProb p1) {
    constexpr int KC = 32;
    constexpr int AST = 40;
    constexpr int MI = BR / 32;
    constexpr int NCW = NCOLS / 4;
    constexpr int NT = NCW / 8;
    constexpr int NG = (NT + 1) / 2;
    constexpr int APT = BR * KC / 256;
    constexpr int WPT = NCOLS * KC / 256;
    const GemmProb& p = blockIdx.y ? p1 : p0;
    const int row0 = blockIdx.x * BR;
    if (row0 >= p.M) return;

    __shared__ __half As[2][BR][AST];
    __shared__ __half Ws[2][NCOLS][AST];

    const int M = p.M;
    const int K1 = p.K1, K2 = p.K2;
    const __half* A = p.A;
    const __half* B = p.B;

    const int t = threadIdx.x;
    const int lane = t & 31;
    const int wid = t >> 5;
    const int warp_m = wid >> 2;
    const int warp_n = wid & 3;
    const int grp = lane >> 2;
    const int qid = lane & 3;
    const int lr = (BR == 128) ? (t >> 1) : (t >> 2);
    const int lk = (BR == 128) ? ((t & 1) * 16) : ((t & 3) * 8);
    const int grow = row0 + lr;
    const int wn = (NCOLS == 128) ? (t >> 1) : (t >> 2);
    const int wk = (NCOLS == 128) ? ((t & 1) * 16) : ((t & 3) * 8);
    const int lm_r = (lane & 7) + ((lane >> 3) & 1) * 8;
    const int lm_c = ((lane >> 4) & 1) * 8;

    const int n1 = K1 / KC;
    const int n2 = (B != nullptr) ? (K2 / KC) : 0;
    const int nch = n1 + n2;

    uint4 pa0 = make_uint4(0, 0, 0, 0), pa1 = make_uint4(0, 0, 0, 0);
    uint4 pw0 = make_uint4(0, 0, 0, 0), pw1 = make_uint4(0, 0, 0, 0);

    auto loadX = [&](int cc) {
        const __half* Xp; int stride, k0;
        if (cc < n1) { Xp = A; stride = K1; k0 = cc * KC; }
        else         { Xp = B; stride = K2; k0 = (cc - n1) * KC; }
        pa0 = make_uint4(0, 0, 0, 0); pa1 = pa0;
        if (grow < M) {
            const __half* base = Xp + (size_t)grow * stride + k0 + lk;
            pa0 = *(const uint4*)base;
            if (APT == 16) pa1 = *(const uint4*)(base + 8);
        }
    };
    auto loadW = [&](int cc) {
        const __half* Wp; int stride, k0;
        if (cc < n1) { Wp = p.W1; stride = K1; k0 = cc * KC; }
        else         { Wp = p.W2; stride = K2; k0 = (cc - n1) * KC; }
        const __half* base = Wp + (size_t)wn * stride + k0 + wk;
        pw0 = *(const uint4*)base;
        if (WPT == 16) pw1 = *(const uint4*)(base + 8);
    };
    auto stage = [&](int buf) {
        *(uint4*)&As[buf][lr][lk] = pa0;
        if (APT == 16) *(uint4*)&As[buf][lr][lk + 8] = pa1;
        *(uint4*)&Ws[buf][wn][wk] = pw0;
        if (WPT == 16) *(uint4*)&Ws[buf][wn][wk + 8] = pw1;
    };

    float acc[MI][NT][4];
#pragma unroll
    for (int mi = 0; mi < MI; mi++)
#pragma unroll
        for (int ni = 0; ni < NT; ni++)
#pragma unroll
            for (int c = 0; c < 4; c++) acc[mi][ni][c] = 0.f;

    loadX(0); loadW(0); stage(0);

    for (int cc = 0; cc < nch; ++cc) {
        const int buf = cc & 1;
        __syncthreads();
        if (cc + 1 < nch) { loadX(cc + 1); loadW(cc + 1); }
#pragma unroll
        for (int ks = 0; ks < KC; ks += 16) {
            unsigned bf[NG][4];
#pragma unroll
            for (int g = 0; g < NG; g++) {
                int c = warp_n * NCW + g * 16;
                LDSM_X4(bf[g][0], bf[g][1], bf[g][2], bf[g][3],
                        smem_u32(&Ws[buf][c + lm_r][ks + lm_c]));
            }
#pragma unroll
            for (int mi = 0; mi < MI; mi++) {
                unsigned af[4];
                int r = warp_m * (16 * MI) + mi * 16;
                LDSM_X4(af[0], af[1], af[2], af[3],
                        smem_u32(&As[buf][r + lm_r][ks + lm_c]));
#pragma unroll
                for (int g = 0; g < NG; g++) {
#pragma unroll
                    for (int half = 0; half < 2; half++) {
                        int ni = g * 2 + half;
                        if (ni < NT)
                            MMA_F16(acc[mi][ni], af, bf[g][half], bf[g][half + 2]);
                    }
                }
            }
        }
        if (cc + 1 < nch) stage(buf ^ 1);
    }

#pragma unroll
    for (int ni = 0; ni < NT; ni++) {
        int cb = warp_n * NCW + ni * 8 + 2 * qid;
        float2 bv = make_float2(0.f, 0.f);
        if (p.bias != nullptr) bv = *(const float2*)(p.bias + cb);
#pragma unroll
        for (int mi = 0; mi < MI; mi++) {
            int r0 = row0 + warp_m * (16 * MI) + mi * 16 + grp;
            float v0 = acc[mi][ni][0] + bv.x;
            float v1 = acc[mi][ni][1] + bv.y;
            float v2 = acc[mi][ni][2] + bv.x;
            float v3 = acc[mi][ni][3] + bv.y;
            if (p.relu) {
                v0 = fmaxf(v0, 0.f); v1 = fmaxf(v1, 0.f);
                v2 = fmaxf(v2, 0.f); v3 = fmaxf(v3, 0.f);
            }
            __half2 h0 = __floats2half2_rn(v0, v1);
            __half2 h1 = __floats2half2_rn(v2, v3);
            if (r0 < M)     *(__half2*)(p.Y + (size_t)r0 * NCOLS + cb) = h0;
            if (r0 + 8 < M) *(__half2*)(p.Y + (size_t)(r0 + 8) * NCOLS + cb) = h1;
        }
    }
}

// ---------------- chained GEMM: Y2 = (relu(A@W1 + B@W2 + b)) @ W3 + b3 ----------
struct ChainProb {
    const __half* A; int K1;
    const __half* B; int K2;
    const __half* W1; const __half* W2;
    const float* bias;
    const __half* W3;
    const float* bias3;
    __half* Y2;
    int M;
};

__global__ __launch_bounds__(512, 1)
void chain_h(ChainProb p0, ChainProb p1) {
    constexpr int KC = 32;
    constexpr int AST = 40;
    constexpr int BR = 128;
    constexpr int NCOLS = 128;
    constexpr int NCW = 32;
    constexpr int NT = 4;
    constexpr int NG = 2;
    const ChainProb& p = blockIdx.y ? p1 : p0;
    const int row0 = blockIdx.x * BR;
    if (row0 >= p.M) return;

    __shared__ __half As[2][BR][AST];
    __shared__ __half Ws[2][NCOLS][AST];

    const int M = p.M;
    const int K1 = p.K1, K2 = p.K2;

    const int t = threadIdx.x;
    const int lane = t & 31;
    const int wid = t >> 5;
    const int warp_m = wid >> 2;
    const int warp_n = wid & 3;
    const int grp = lane >> 2;
    const int qid = lane & 3;
    const int lr = t >> 2;
    const int lk = (t & 3) * 8;
    const int grow = row0 + lr;
    const int wn = t >> 2;
    const int wk = (t & 3) * 8;
    const int lm_r = (lane & 7) + ((lane >> 3) & 1) * 8;
    const int lm_c = ((lane >> 4) & 1) * 8;

    const int n1 = K1 / KC;
    const int n2 = K2 / KC;
    const int nch = n1 + n2;

    uint4 pa = make_uint4(0, 0, 0, 0), pw = make_uint4(0, 0, 0, 0);

    auto loadX = [&](int cc) {
        const __half* Xp; int stride, k0;
        if (cc < n1) { Xp = p.A; stride = K1; k0 = cc * KC; }
        else         { Xp = p.B; stride = K2; k0 = (cc - n1) * KC; }
        pa = make_uint4(0, 0, 0, 0);
        if (grow < M) pa = *(const uint4*)(Xp + (size_t)grow * stride + k0 + lk);
    };
    auto loadW = [&](int cc) {
        const __half* Wp; int stride, k0;
        if (cc < n1) { Wp = p.W1; stride = K1; k0 = cc * KC; }
        else         { Wp = p.W2; stride = K2; k0 = (cc - n1) * KC; }
        pw = *(const uint4*)(Wp + (size_t)wn * stride + k0 + wk);
    };
    auto stage = [&](int buf) {
        *(uint4*)&As[buf][lr][lk] = pa;
        *(uint4*)&Ws[buf][wn][wk] = pw;
    };

    float acc[2][NT][4];
#pragma unroll
    for (int mi = 0; mi < 2; mi++)
#pragma unroll
        for (int ni = 0; ni < NT; ni++)
#pragma unroll
            for (int c = 0; c < 4; c++) acc[mi][ni][c] = 0.f;

    loadX(0); loadW(0); stage(0);

    for (int cc = 0; cc < nch; ++cc) {
        const int buf = cc & 1;
        __syncthreads();
        if (cc + 1 < nch) { loadX(cc + 1); loadW(cc + 1); }
#pragma unroll
        for (int ks = 0; ks < KC; ks += 16) {
            unsigned af[2][4];
#pragma unroll
            for (int mi = 0; mi < 2; mi++) {
                int r = warp_m * 32 + mi * 16;
                LDSM_X4(af[mi][0], af[mi][1], af[mi][2], af[mi][3],
                        smem_u32(&As[buf][r + lm_r][ks + lm_c]));
            }
            unsigned bf[NG][4];
#pragma unroll
            for (int g = 0; g < NG; g++) {
                int c = warp_n * NCW + g * 16;
                LDSM_X4(bf[g][0], bf[g][1], bf[g][2], bf[g][3],
                        smem_u32(&Ws[buf][c + lm_r][ks + lm_c]));
            }
#pragma unroll
            for (int g = 0; g < NG; g++) {
#pragma unroll
                for (int half = 0; half < 2; half++) {
#pragma unroll
                    for (int mi = 0; mi < 2; mi++)
                        MMA_F16(acc[mi][g * 2 + half], af[mi], bf[g][half], bf[g][half + 2]);
                }
            }
        }
        if (cc + 1 < nch) stage(buf ^ 1);
    }

    float acc2[2][2][4];
#pragma unroll
    for (int mi = 0; mi < 2; mi++)
#pragma unroll
        for (int ni = 0; ni < 2; ni++)
#pragma unroll
            for (int c = 0; c < 4; c++) acc2[mi][ni][c] = 0.f;

#pragma unroll 1
    for (int cc2 = 0; cc2 < 4; ++cc2) {
        const int buf = cc2 & 1;
        __syncthreads();
        if (warp_n == cc2) {
#pragma unroll
            for (int mi = 0; mi < 2; mi++)
#pragma unroll
                for (int ni = 0; ni < NT; ni++) {
                    int cl = ni * 8 + 2 * qid;
                    float2 bv = *(const float2*)(p.bias + warp_n * 32 + cl);
                    float v0 = fmaxf(acc[mi][ni][0] + bv.x, 0.f);
                    float v1 = fmaxf(acc[mi][ni][1] + bv.y, 0.f);
                    float v2 = fmaxf(acc[mi][ni][2] + bv.x, 0.f);
                    float v3 = fmaxf(acc[mi][ni][3] + bv.y, 0.f);
                    __half2 h0 = __floats2half2_rn(v0, v1);
                    __half2 h1 = __floats2half2_rn(v2, v3);
                    int r = warp_m * 32 + mi * 16 + grp;
                    *(__half2*)&As[buf][r][cl] = h0;
                    *(__half2*)&As[buf][r + 8][cl] = h1;
                }
        }
        {
            int wn2 = t >> 3;
            int wk2 = (t & 7) * 4;
            *(uint2*)&Ws[buf][wn2][wk2] =
                *(const uint2*)(p.W3 + (size_t)wn2 * 128 + cc2 * 32 + wk2);
        }
        __syncthreads();
#pragma unroll
        for (int ks = 0; ks < KC; ks += 16) {
            unsigned af2[2][4];
#pragma unroll
            for (int mi = 0; mi < 2; mi++) {
                int r = warp_m * 32 + mi * 16;
                LDSM_X4(af2[mi][0], af2[mi][1], af2[mi][2], af2[mi][3],
                        smem_u32(&As[buf][r + lm_r][ks + lm_c]));
            }
            unsigned bf2[4];
            LDSM_X4(bf2[0], bf2[1], bf2[2], bf2[3],
                    smem_u32(&Ws[buf][warp_n * 16 + lm_r][ks + lm_c]));
#pragma unroll
            for (int half = 0; half < 2; half++) {
                MMA_F16(acc2[0][half], af2[0], bf2[half], bf2[half + 2]);
                MMA_F16(acc2[1][half], af2[1], bf2[half], bf2[half + 2]);
            }
        }
    }

#pragma unroll
    for (int ni = 0; ni < 2; ni++) {
        int cb = warp_n * 16 + ni * 8 + 2 * qid;
        float2 bv = *(const float2*)(p.bias3 + cb);
#pragma unroll
        for (int mi = 0; mi < 2; mi++) {
            int r0 = row0 + warp_m * 32 + mi * 16 + grp;
            __half2 h0 = __floats2half2_rn(acc2[mi][ni][0] + bv.x, acc2[mi][ni][1] + bv.y);
            __half2 h1 = __floats2half2_rn(acc2[mi][ni][2] + bv.x, acc2[mi][ni][3] + bv.y);
            if (r0 < M)     *(__half2*)(p.Y2 + (size_t)r0 * 64 + cb) = h0;
            if (r0 + 8 < M) *(__half2*)(p.Y2 + (size_t)(r0 + 8) * 64 + cb) = h1;
        }
    }
}

// ---------------- fused edge decoder (fp16 mma + ldmatrix, KC=32) ---------------
__global__ __launch_bounds__(512, 2)
void dec_h(int M, const __half* __restrict__ zod, const __half* __restrict__ zdt,
           const int* __restrict__ esrc, const int* __restrict__ edst,
           const __half* __restrict__ Wt, const float* __restrict__ b1,
           const float* __restrict__ w2, const float* __restrict__ b2p,
           float* __restrict__ out) {
    constexpr int NC = 64;
    constexpr int BR = 128;
    constexpr int K = 128;
    constexpr int KC = 32;
    constexpr int AST = 40;
    constexpr int NCW = 16;
    constexpr int NT = 2;
    constexpr int NCH = K / KC;
    __shared__ __half As[2][BR][AST];
    __shared__ __half Ws[2][NC][AST];
    __shared__ float Red[BR][17];

    const int t = threadIdx.x;
    const int lane = t & 31;
    const int wid = t >> 5;
    const int warp_m = wid >> 2;
    const int warp_n = wid & 3;
    const int grp = lane >> 2;
    const int qid = lane & 3;
    const int row0 = blockIdx.x * BR;
    const int lr = t >> 2;
    const int lk = (t & 3) * 8;
    const int grow = row0 + lr;
    const int wn = t >> 3;
    const int wk = (t & 7) * 4;
    const int lm_r = (lane & 7) + ((lane >> 3) & 1) * 8;
    const int lm_c = ((lane >> 4) & 1) * 8;

    int si = 0, di = 0;
    if (grow < M) { si = __ldg(esrc + grow); di = __ldg(edst + grow); }

    uint4 pa = make_uint4(0, 0, 0, 0);
    uint2 pwv = make_uint2(0, 0);

    auto loadX = [&](int cc) {
        pa = make_uint4(0, 0, 0, 0);
        if (grow < M) {
            int k = cc * KC + lk;
            const __half* base = (k < 64) ? (zod + (size_t)si * 64 + k)
                                          : (zdt + (size_t)di * 64 + (k - 64));
            pa = *(const uint4*)base;
        }
    };
    auto loadW = [&](int cc) {
        pwv = *(const uint2*)(Wt + (size_t)wn * K + cc * KC + wk);
    };
    auto stage = [&](int buf) {
        *(uint4*)&As[buf][lr][lk] = pa;
        *(uint2*)&Ws[buf][wn][wk] = pwv;
    };

    float acc[2][NT][4];
#pragma unroll
    for (int mi = 0; mi < 2; mi++)
#pragma unroll
        for (int ni = 0; ni < NT; ni++)
#pragma unroll
            for (int c = 0; c < 4; c++) acc[mi][ni][c] = 0.f;

    loadX(0); loadW(0); stage(0);

#pragma unroll 1
    for (int cc = 0; cc < NCH; ++cc) {
        const int buf = cc & 1;
        __syncthreads();
        if (cc + 1 < NCH) { loadX(cc + 1); loadW(cc + 1); }
#pragma unroll
        for (int ks = 0; ks < KC; ks += 16) {
            unsigned af[2][4];
#pragma unroll
            for (int mi = 0; mi < 2; mi++) {
                int r = warp_m * 32 + mi * 16;
                LDSM_X4(af[mi][0], af[mi][1], af[mi][2], af[mi][3],
                        smem_u32(&As[buf][r + lm_r][ks + lm_c]));
            }
            unsigned bf[4];
            {
                int c = warp_n * NCW;
                LDSM_X4(bf[0], bf[1], bf[2], bf[3],
                        smem_u32(&Ws[buf][c + lm_r][ks + lm_c]));
            }
#pragma unroll
            for (int half = 0; half < 2; half++) {
                unsigned b0 = bf[half];
                unsigned b1 = bf[half + 2];
                MMA_F16(acc[0][half], af[0], b0, b1);
                MMA_F16(acc[1][half], af[1], b0, b1);
            }
        }
        if (cc + 1 < NCH) stage(buf ^ 1);
    }

    float p[2][2] = {{0.f, 0.f}, {0.f, 0.f}};
#pragma unroll
    for (int ni = 0; ni < NT; ni++) {
        int cb = warp_n * NCW + ni * 8 + 2 * qid;
        float2 bv = *(const float2*)(b1 + cb);
        float2 wv = *(const float2*)(w2 + cb);
#pragma unroll
        for (int mi = 0; mi < 2; mi++) {
            p[mi][0] += fmaxf(acc[mi][ni][0] + bv.x, 0.f) * wv.x
                      + fmaxf(acc[mi][ni][1] + bv.y, 0.f) * wv.y;
            p[mi][1] += fmaxf(acc[mi][ni][2] + bv.x, 0.f) * wv.x
                      + fmaxf(acc[mi][ni][3] + bv.y, 0.f) * wv.y;
        }
    }
    __syncthreads();
#pragma unroll
    for (int mi = 0; mi < 2; mi++) {
        Red[warp_m * 32 + mi * 16 + grp    ][warp_n * 4 + qid] = p[mi][0];
        Red[warp_m * 32 + mi * 16 + grp + 8][warp_n * 4 + qid] = p[mi][1];
    }
    __syncthreads();
    if (t < BR) {
        int r = row0 + t;
        if (r < M) {
            float s = 0.f;
#pragma unroll
            for (int j = 0; j < 16; j++) s += Red[t][j];
            out[r] = 1.f / (1.f + expf(-(s + b2p[0])));
        }
    }
}

// ---------------- host orchestration --------------------------------------------
extern "C" void kernel_launch(void* const* d_in, const int* in_sizes, int n_in,
                              void* d_out, int out_size) {
    const float* x_dt   = (const float*)d_in[0];
    const float* x_od   = (const float*)d_in[1];
    const int*   ei_dt  = (const int*)  d_in[2];
    const int*   rsrc   = (const int*)  d_in[3];
    const int*   rdst   = (const int*)  d_in[4];
    const int*   elsrc  = (const int*)  d_in[5];
    const int*   eldst  = (const int*)  d_in[6];
    const float* od1_wl = (const float*)d_in[7];
    const float* od1_wr = (const float*)d_in[8];
    const float* od1_b  = (const float*)d_in[9];
    const float* od2_wl = (const float*)d_in[10];
    const float* od2_wr = (const float*)d_in[11];
    const float* od2_b  = (const float*)d_in[12];
    const float* od3_wl = (const float*)d_in[13];
    const float* od3_wr = (const float*)d_in[14];
    const float* od3_b  = (const float*)d_in[15];
    const float* od_lw  = (const float*)d_in[16];
    const float* od_lb  = (const float*)d_in[17];
    const float* dt1_wl = (const float*)d_in[18];
    const float* dt1_wr = (const float*)d_in[19];
    const float* dt1_b  = (const float*)d_in[20];
    const float* dt2_wl = (const float*)d_in[21];
    const float* dt2_wr = (const float*)d_in[22];
    const float* dt2_b  = (const float*)d_in[23];
    const float* dt_lw  = (const float*)d_in[24];
    const float* dt_lb  = (const float*)d_in[25];
    const float* dec_w1 = (const float*)d_in[26];
    const float* dec_b1 = (const float*)d_in[27];
    const float* dec_w2 = (const float*)d_in[28];
    const float* dec_b2 = (const float*)d_in[29];
    float* out = (float*)d_out;

    const int E1 = in_sizes[2] / 2;
    const int E2 = in_sizes[3];
    const int EL = in_sizes[5];
    const int* r1 = ei_dt;
    const int* c1 = ei_dt + E1;

    __half *xdth, *xodh, *acc1, *acc2, *acc3, *h, *d1, *od2b, *zodh, *zdth, *wh;
    int *deg1, *rp1, *fill1, *es1, *deg2, *rp2, *fill2, *es2, *part1, *part2, *scnt;
    cudaGetSymbolAddress((void**)&xdth, g_xdth);
    cudaGetSymbolAddress((void**)&xodh, g_xodh);
    cudaGetSymbolAddress((void**)&acc1, g_acc1);
    cudaGetSymbolAddress((void**)&acc2, g_acc2);
    cudaGetSymbolAddress((void**)&acc3, g_acc3);
    cudaGetSymbolAddress((void**)&h,   g_h);
    cudaGetSymbolAddress((void**)&d1,  g_d1);
    cudaGetSymbolAddress((void**)&od2b, g_od2);
    cudaGetSymbolAddress((void**)&zodh, g_zodh);
    cudaGetSymbolAddress((void**)&zdth, g_zdth);
    cudaGetSymbolAddress((void**)&wh,  g_wh);
    cudaGetSymbolAddress((void**)&deg1, g_deg1);
    cudaGetSymbolAddress((void**)&rp1, g_rp1);
    cudaGetSymbolAddress((void**)&fill1, g_fill1);
    cudaGetSymbolAddress((void**)&es1, g_es1);
    cudaGetSymbolAddress((void**)&deg2, g_deg2);
    cudaGetSymbolAddress((void**)&rp2, g_rp2);
    cudaGetSymbolAddress((void**)&fill2, g_fill2);
    cudaGetSymbolAddress((void**)&es2, g_es2);
    cudaGetSymbolAddress((void**)&part1, g_part1);
    cudaGetSymbolAddress((void**)&part2, g_part2);
    cudaGetSymbolAddress((void**)&scnt, g_scan_cnt);

    const int TB = 256;
    const int tiles1 = cdiv(NDT, TILE);
    const int tiles2 = cdiv(NOD, TILE);

    // ---- fused prep: weights transpose/convert + input convert + zeroing ----
    WTList L;
    const float* ws[13] = {od1_wl, od1_wr, dt1_wl, dt1_wr, od2_wl, od2_wr,
                           od3_wl, od3_wr, od_lw, dt2_wl, dt2_wr, dt_lw, dec_w1};
    int Ks[13] = {128, 128, 128, 128, 128, 64, 128, 128, 128, 128, 128, 128, 128};
    int Ns[13] = {128, 128, 128, 128, 128, 128, 128, 128, 64, 128, 128, 64, 64};
    int wt_tot = 0;
    for (int i = 0; i < 13; i++) {
        L.src[i] = ws[i]; L.K[i] = Ks[i]; L.N[i] = Ns[i];
        wt_tot += Ks[i] * Ns[i];
    }
    int prep_items = wt_tot + NDT * 32 + NOD * 16 + NDT / 4 + NOD / 4 + 1;
    k_prep<<<cdiv(prep_items, TB), TB>>>(L, wh, wt_tot, x_dt, xdth, x_od, xodh,
                                         deg1, deg2, scnt);
#define WT(i) (wh + (size_t)(i) * WSLOT)

    // ---- CSR build (edge kernels: 4 edges/thread) ----
    k_degree2<<<cdiv((long long)(E1 + E2), TB * 4), TB>>>(c1, E1, deg1, rdst, E2, deg2);
    k_scan<<<tiles1 + tiles2, TB>>>(deg1, NDT, rp1, fill1, part1, tiles1,
                                    deg2, NOD, rp2, fill2, part2, tiles2, scnt);
    k_reorder2<<<cdiv((long long)(E1 + E2), TB * 4), TB>>>(r1, c1, E1, fill1, es1,
                                                           rsrc, rdst, E2, fill2, es2);

    // ---- pipeline ----
    k_aggh2<<<cdiv((long long)NDT * 32, TB), TB>>>(
        xdth, es1, rp1, acc1, NDT, nullptr, nullptr, nullptr, nullptr, 0);

    GemmProb ph  = {acc1, 128, xdth, 128, WT(0), WT(1), od1_b, h,  NDT, 1};
    GemmProb pd1 = {acc1, 128, xdth, 128, WT(2), WT(3), dt1_b, d1, NDT, 1};
    gemm_h<128, 128><<<dim3(cdiv(NDT, 128), 2), 256>>>(ph, pd1);

    k_aggh2<<<cdiv((long long)(NOD + NDT) * 32, TB), TB>>>(
        h, es2, rp2, acc2, NOD, d1, es1, rp1, acc3, NDT);

    GemmProb pod2 = {acc2, 128, xodh, 64, WT(4), WT(5), od2_b, od2b, NOD, 1};
    gemm_h<128, 64><<<dim3(cdiv(NOD, 64), 1), 256>>>(pod2, pod2);

    ChainProb cod = {acc2, 128, od2b, 128, WT(6), WT(7), od3_b, WT(8), od_lb, zodh, NOD};
    ChainProb cdt = {acc3, 128, d1, 128, WT(9), WT(10), dt2_b, WT(11), dt_lb, zdth, NDT};
    chain_h<<<dim3(cdiv(NDT, 128), 2), 512>>>(cdt, cod);

    dec_h<<<cdiv(EL, 128), 512>>>(EL, zodh, zdth, elsrc, eldst,
                                  WT(12), dec_b1, dec_w2, dec_b2, out);
}

// round 15
// speedup vs baseline: 1.0013x; 1.0013x over previous
#include <cuda_runtime.h>
#include <cuda_fp16.h>
#include <math.h>

#define NDT 30000
#define NOD 10000
#define WSLOT 16384
#define TILE 1024

static inline int cdiv(long long a, long long b) { return (int)((a + b - 1) / b); }

// ---------------- fp16 mma / ldmatrix helpers -----------------------------------
#define MMA_F16(d, a, b0, b1)                                              \
    asm volatile("mma.sync.aligned.m16n8k16.row.col.f32.f16.f16.f32 "      \
                 "{%0,%1,%2,%3}, {%4,%5,%6,%7}, {%8,%9}, {%0,%1,%2,%3};"   \
                 : "+f"((d)[0]), "+f"((d)[1]), "+f"((d)[2]), "+f"((d)[3])  \
                 : "r"((a)[0]), "r"((a)[1]), "r"((a)[2]), "r"((a)[3]),     \
                   "r"(b0), "r"(b1))

#define LDSM_X4(r0, r1, r2, r3, addr)                                      \
    asm volatile("ldmatrix.sync.aligned.m8n8.x4.shared.b16 "               \
                 "{%0,%1,%2,%3}, [%4];"                                    \
                 : "=r"(r0), "=r"(r1), "=r"(r2), "=r"(r3) : "r"(addr))

__device__ __forceinline__ unsigned smem_u32(const void* p) {
    return (unsigned)__cvta_generic_to_shared(p);
}

// ---------------- device scratch ------------------------------------------------
__device__ __half g_xdth[NDT * 128];
__device__ __half g_xodh[NOD * 64];
__device__ __half g_acc1[NDT * 128];
__device__ __half g_acc2[NOD * 128];
__device__ __half g_acc3[NDT * 128];
__device__ __half g_h [NDT * 128];
__device__ __half g_d1[NDT * 128];
__device__ __half g_zodh[NOD * 64];
__device__ __half g_zdth[NDT * 64];
__device__ __half g_wh[13 * WSLOT];
// CSR scratch
__device__ int g_deg1[NDT];
__device__ int g_rp1[NDT + 1];
__device__ int g_fill1[NDT];
__device__ int g_es1[500000];
__device__ int g_deg2[NOD];
__device__ int g_rp2[NOD + 1];
__device__ int g_fill2[NOD];
__device__ int g_es2[300000];
__device__ int g_part1[64];
__device__ int g_part2[64];
__device__ int g_scan_cnt;

// ---------------- fused prep: weight transpose + input convert + zeroing --------
struct WTList {
    const float* src[13];
    int K[13];
    int N[13];
};
__global__ void k_prep(WTList L, __half* __restrict__ wdst, int wt_tot,
                       const float* __restrict__ x_dt, __half* __restrict__ xdh,
                       const float* __restrict__ x_od, __half* __restrict__ xoh,
                       int* __restrict__ deg1, int* __restrict__ deg2,
                       int* __restrict__ cnt) {
    int i = blockIdx.x * blockDim.x + threadIdx.x;
    if (i < wt_tot) {
        int s = 0, off = i;
        while (off >= L.K[s] * L.N[s]) { off -= L.K[s] * L.N[s]; s++; }
        int K = L.K[s];
        int n = off / K, k = off - n * K;
        wdst[(size_t)s * WSLOT + off] = __float2half(L.src[s][k * L.N[s] + n]);
        return;
    }
    i -= wt_tot;
    const int n1 = NDT * 128 / 4, n2 = NOD * 64 / 4;
    const int z1 = NDT / 4, z2 = NOD / 4;
    if (i < n1) {
        float4 v = *(const float4*)(x_dt + i * 4);
        __half2 h0 = __floats2half2_rn(v.x, v.y);
        __half2 h1 = __floats2half2_rn(v.z, v.w);
        *(uint2*)(xdh + i * 4) = make_uint2(*(unsigned*)&h0, *(unsigned*)&h1);
    } else if (i < n1 + n2) {
        int j = i - n1;
        float4 v = *(const float4*)(x_od + j * 4);
        __half2 h0 = __floats2half2_rn(v.x, v.y);
        __half2 h1 = __floats2half2_rn(v.z, v.w);
        *(uint2*)(xoh + j * 4) = make_uint2(*(unsigned*)&h0, *(unsigned*)&h1);
    } else if (i < n1 + n2 + z1) {
        ((int4*)deg1)[i - (n1 + n2)] = make_int4(0, 0, 0, 0);
    } else if (i < n1 + n2 + z1 + z2) {
        ((int4*)deg2)[i - (n1 + n2 + z1)] = make_int4(0, 0, 0, 0);
    } else if (i == n1 + n2 + z1 + z2) {
        *cnt = 0;
    }
}

// ---------------- CSR build (R13 form: 1 edge/thread) ----------------------------
__global__ void k_degree2(const int* __restrict__ c1, int E1, int* __restrict__ deg1,
                          const int* __restrict__ rdst, int E2, int* __restrict__ deg2) {
    int i = blockIdx.x * blockDim.x + threadIdx.x;
    if (i < E1) atomicAdd(deg1 + __ldg(c1 + i), 1);
    else if (i < E1 + E2) atomicAdd(deg2 + __ldg(rdst + (i - E1)), 1);
}

// fused two-phase scan with device-wide spin barrier (40 blocks, all resident).
// fill[i] initialized to rp[i] so reorder atomicAdds it directly.
__global__ void k_scan(const int* __restrict__ deg1, int n1, int* __restrict__ rp1,
                       int* __restrict__ fill1, int* __restrict__ part1, int tiles1,
                       const int* __restrict__ deg2, int n2, int* __restrict__ rp2,
                       int* __restrict__ fill2, int* __restrict__ part2, int tiles2,
                       int* __restrict__ cnt) {
    int b = blockIdx.x;
    const int* deg; int n; int* rp; int* fill; int* part; int tt, tiles;
    if (b < tiles1) { deg = deg1; n = n1; rp = rp1; fill = fill1; part = part1; tt = b; tiles = tiles1; }
    else { deg = deg2; n = n2; rp = rp2; fill = fill2; part = part2; tt = b - tiles1; tiles = tiles2; }
    __shared__ int wsum[8];
    __shared__ int s_off;
    int t = threadIdx.x, lane = t & 31, w = t >> 5;
    int base = tt * TILE + t * 4;
    int d[4]; int tot = 0;
#pragma unroll
    for (int j = 0; j < 4; j++) { d[j] = (base + j < n) ? deg[base + j] : 0; tot += d[j]; }
    int inc = tot;
#pragma unroll
    for (int o = 1; o < 32; o <<= 1) {
        int u = __shfl_up_sync(0xffffffffu, inc, o);
        if (lane >= o) inc += u;
    }
    if (lane == 31) wsum[w] = inc;
    __syncthreads();
    if (t == 0) {
        int s = 0;
#pragma unroll
        for (int j = 0; j < 8; j++) s += wsum[j];
        part[tt] = s;
        __threadfence();
        atomicAdd(cnt, 1);
        while (atomicAdd(cnt, 0) < tiles1 + tiles2) {}
        __threadfence();
    }
    __syncthreads();
    if (t < 32) {
        int v = (t < tt) ? atomicAdd(part + t, 0) : 0;
#pragma unroll
        for (int o = 16; o; o >>= 1) v += __shfl_xor_sync(0xffffffffu, v, o);
        if (t == 0) s_off = v;
    }
    __syncthreads();
    int woff = 0;
#pragma unroll
    for (int j = 0; j < 8; j++) if (j < w) woff += wsum[j];
    int run = s_off + woff + inc - tot;
#pragma unroll
    for (int j = 0; j < 4; j++) {
        if (base + j < n) { rp[base + j] = run; fill[base + j] = run; run += d[j]; }
    }
    if (tt == tiles - 1 && t == blockDim.x - 1) rp[n] = run;
}

// direct-offset reorder (R13 form: 1 edge/thread)
__global__ void k_reorder2(const int* __restrict__ s1, const int* __restrict__ t1, int E1,
                           int* __restrict__ f1, int* __restrict__ e1,
                           const int* __restrict__ s2, const int* __restrict__ t2, int E2,
                           int* __restrict__ f2, int* __restrict__ e2) {
    int i = blockIdx.x * blockDim.x + threadIdx.x;
    if (i < E1) {
        int d = __ldg(t1 + i);
        int pos = atomicAdd(f1 + d, 1);
        e1[pos] = __ldg(s1 + i);
    } else if (i < E1 + E2) {
        int j = i - E1;
        int d = __ldg(t2 + j);
        int pos = atomicAdd(f2 + d, 1);
        e2[pos] = __ldg(s2 + j);
    }
}

// ---------------- mean aggregation: warp per dst, 4 edges in flight -------------
__global__ __launch_bounds__(256)
void k_aggh2(const __half* __restrict__ X1, const int* __restrict__ es1,
             const int* __restrict__ rp1, __half* __restrict__ acc1, int n1,
             const __half* __restrict__ X2, const int* __restrict__ es2,
             const int* __restrict__ rp2, __half* __restrict__ acc2, int n2) {
    int w = (blockIdx.x * blockDim.x + threadIdx.x) >> 5;
    const __half* X; const int* es; const int* rowptr; __half* acc;
    if (w < n1) { X = X1; es = es1; rowptr = rp1; acc = acc1; }
    else if (w < n1 + n2) { X = X2; es = es2; rowptr = rp2; acc = acc2; w -= n1; }
    else return;
    int lane = threadIdx.x & 31;
    int grp4 = lane >> 3;
    int sub = lane & 7;
    int beg = __ldg(rowptr + w);
    int end = __ldg(rowptr + w + 1);
    float s[16];
#pragma unroll
    for (int k = 0; k < 16; k++) s[k] = 0.f;
    for (int base = beg; base < end; base += 32) {
        int p = 0;
        if (base + lane < end) p = __ldg(es + base + lane);
        int cnt = min(32, end - base);
        for (int j = 0; j < cnt; j += 4) {
            int e = j + grp4;
            int sr = __shfl_sync(0xffffffffu, p, e);
            if (e < cnt) {
                const uint4* row = (const uint4*)(X + (size_t)sr * 128 + sub * 16);
                uint4 v0 = __ldg(row);
                uint4 v1 = __ldg(row + 1);
                unsigned vv[8] = {v0.x, v0.y, v0.z, v0.w, v1.x, v1.y, v1.z, v1.w};
#pragma unroll
                for (int k = 0; k < 8; k++) {
                    float2 f = __half22float2(*(__half2*)&vv[k]);
                    s[2 * k] += f.x;
                    s[2 * k + 1] += f.y;
                }
            }
        }
    }
#pragma unroll
    for (int k = 0; k < 16; k++) {
        s[k] += __shfl_xor_sync(0xffffffffu, s[k], 8);
        s[k] += __shfl_xor_sync(0xffffffffu, s[k], 16);
    }
    if (grp4 == 0) {
        float inv = 1.f / fmaxf((float)(end - beg), 1.f);
        unsigned o[8];
#pragma unroll
        for (int k = 0; k < 8; k++) {
            __half2 hv = __floats2half2_rn(s[2 * k] * inv, s[2 * k + 1] * inv);
            o[k] = *(unsigned*)&hv;
        }
        uint4* dst = (uint4*)(acc + (size_t)w * 128 + sub * 16);
        dst[0] = make_uint4(o[0], o[1], o[2], o[3]);
        dst[1] = make_uint4(o[4], o[5], o[6], o[7]);
    }
}

// ---------------- generic 2-problem fp16 GEMM (256 thr, 2m x 4n warps) ----------
struct GemmProb {
    const __half* A; int K1;
    const __half* B; int K2;
    const __half* W1; const __half* W2;   // pre-transposed [N][K] f16
    const float* bias;
    __half* Y;
    int M;
    int relu;
};

template <int NCOLS, int BR>
__global__ __launch_bounds__(256, 2)
void gemm_h(GemmProb p0, GemmProb p1) {
    constexpr int KC = 32;
    constexpr int AST = 40;
    constexpr int MI = BR / 32;
    constexpr int NCW = NCOLS / 4;
    constexpr int NT = NCW / 8;
    constexpr int NG = (NT + 1) / 2;
    constexpr int APT = BR * KC / 256;
    constexpr int WPT = NCOLS * KC / 256;
    const GemmProb& p = blockIdx.y ? p1 : p0;
    const int row0 = blockIdx.x * BR;
    if (row0 >= p.M) return;

    __shared__ __half As[2][BR][AST];
    __shared__ __half Ws[2][NCOLS][AST];

    const int M = p.M;
    const int K1 = p.K1, K2 = p.K2;
    const __half* A = p.A;
    const __half* B = p.B;

    const int t = threadIdx.x;
    const int lane = t & 31;
    const int wid = t >> 5;
    const int warp_m = wid >> 2;
    const int warp_n = wid & 3;
    const int grp = lane >> 2;
    const int qid = lane & 3;
    const int lr = (BR == 128) ? (t >> 1) : (t >> 2);
    const int lk = (BR == 128) ? ((t & 1) * 16) : ((t & 3) * 8);
    const int grow = row0 + lr;
    const int wn = (NCOLS == 128) ? (t >> 1) : (t >> 2);
    const int wk = (NCOLS == 128) ? ((t & 1) * 16) : ((t & 3) * 8);
    const int lm_r = (lane & 7) + ((lane >> 3) & 1) * 8;
    const int lm_c = ((lane >> 4) & 1) * 8;

    const int n1 = K1 / KC;
    const int n2 = (B != nullptr) ? (K2 / KC) : 0;
    const int nch = n1 + n2;

    uint4 pa0 = make_uint4(0, 0, 0, 0), pa1 = make_uint4(0, 0, 0, 0);
    uint4 pw0 = make_uint4(0, 0, 0, 0), pw1 = make_uint4(0, 0, 0, 0);

    auto loadX = [&](int cc) {
        const __half* Xp; int stride, k0;
        if (cc < n1) { Xp = A; stride = K1; k0 = cc * KC; }
        else         { Xp = B; stride = K2; k0 = (cc - n1) * KC; }
        pa0 = make_uint4(0, 0, 0, 0); pa1 = pa0;
        if (grow < M) {
            const __half* base = Xp + (size_t)grow * stride + k0 + lk;
            pa0 = *(const uint4*)base;
            if (APT == 16) pa1 = *(const uint4*)(base + 8);
        }
    };
    auto loadW = [&](int cc) {
        const __half* Wp; int stride, k0;
        if (cc < n1) { Wp = p.W1; stride = K1; k0 = cc * KC; }
        else         { Wp = p.W2; stride = K2; k0 = (cc - n1) * KC; }
        const __half* base = Wp + (size_t)wn * stride + k0 + wk;
        pw0 = *(const uint4*)base;
        if (WPT == 16) pw1 = *(const uint4*)(base + 8);
    };
    auto stage = [&](int buf) {
        *(uint4*)&As[buf][lr][lk] = pa0;
        if (APT == 16) *(uint4*)&As[buf][lr][lk + 8] = pa1;
        *(uint4*)&Ws[buf][wn][wk] = pw0;
        if (WPT == 16) *(uint4*)&Ws[buf][wn][wk + 8] = pw1;
    };

    float acc[MI][NT][4];
#pragma unroll
    for (int mi = 0; mi < MI; mi++)
#pragma unroll
        for (int ni = 0; ni < NT; ni++)
#pragma unroll
            for (int c = 0; c < 4; c++) acc[mi][ni][c] = 0.f;

    loadX(0); loadW(0); stage(0);

    for (int cc = 0; cc < nch; ++cc) {
        const int buf = cc & 1;
        __syncthreads();
        if (cc + 1 < nch) { loadX(cc + 1); loadW(cc + 1); }
#pragma unroll
        for (int ks = 0; ks < KC; ks += 16) {
            unsigned bf[NG][4];
#pragma unroll
            for (int g = 0; g < NG; g++) {
                int c = warp_n * NCW + g * 16;
                LDSM_X4(bf[g][0], bf[g][1], bf[g][2], bf[g][3],
                        smem_u32(&Ws[buf][c + lm_r][ks + lm_c]));
            }
#pragma unroll
            for (int mi = 0; mi < MI; mi++) {
                unsigned af[4];
                int r = warp_m * (16 * MI) + mi * 16;
                LDSM_X4(af[0], af[1], af[2], af[3],
                        smem_u32(&As[buf][r + lm_r][ks + lm_c]));
#pragma unroll
                for (int g = 0; g < NG; g++) {
#pragma unroll
                    for (int half = 0; half < 2; half++) {
                        int ni = g * 2 + half;
                        if (ni < NT)
                            MMA_F16(acc[mi][ni], af, bf[g][half], bf[g][half + 2]);
                    }
                }
            }
        }
        if (cc + 1 < nch) stage(buf ^ 1);
    }

#pragma unroll
    for (int ni = 0; ni < NT; ni++) {
        int cb = warp_n * NCW + ni * 8 + 2 * qid;
        float2 bv = make_float2(0.f, 0.f);
        if (p.bias != nullptr) bv = *(const float2*)(p.bias + cb);
#pragma unroll
        for (int mi = 0; mi < MI; mi++) {
            int r0 = row0 + warp_m * (16 * MI) + mi * 16 + grp;
            float v0 = acc[mi][ni][0] + bv.x;
            float v1 = acc[mi][ni][1] + bv.y;
            float v2 = acc[mi][ni][2] + bv.x;
            float v3 = acc[mi][ni][3] + bv.y;
            if (p.relu) {
                v0 = fmaxf(v0, 0.f); v1 = fmaxf(v1, 0.f);
                v2 = fmaxf(v2, 0.f); v3 = fmaxf(v3, 0.f);
            }
            __half2 h0 = __floats2half2_rn(v0, v1);
            __half2 h1 = __floats2half2_rn(v2, v3);
            if (r0 < M)     *(__half2*)(p.Y + (size_t)r0 * NCOLS + cb) = h0;
            if (r0 + 8 < M) *(__half2*)(p.Y + (size_t)(r0 + 8) * NCOLS + cb) = h1;
        }
    }
}

// ---------------- chained GEMM kernel: dt 2-stage (y=0) / od 3-stage (y=1) ------
// dt: Y1 = relu(acc3@W1 + d1@W2 + b1);  zdt = Y1@W3 + b3
// od: Y0 = relu(acc2@W0a + xod@W0b + b0); Y1 = relu(acc2@W1 + Y0@W2 + b1);
//     zod = Y1@W3 + b3
struct ChainProb {
    const __half* A0; int K0a;            // od stage-0 gmem A (acc2) — null for dt
    const __half* B0; int K0b;            // od stage-0 gmem B (xodh)
    const __half* W0a; const __half* W0b;
    const float* bias0;
    const __half* A1; int K1a;            // stage-1 gmem A
    const __half* B1; int K1b;            // stage-1 gmem B (dt only; od uses Y0 regs)
    const __half* W1; const __half* W2;   // [128][K]
    const float* bias1;
    const __half* W3;                     // [64][128]
    const float* bias3;
    __half* Y2;                           // [M][64]
    int M;
};

__global__ __launch_bounds__(512, 1)
void chain_h(ChainProb pdt, ChainProb pod) {
    constexpr int KC = 32;
    constexpr int AST = 40;
    constexpr int BR = 128;
    constexpr int NCOLS = 128;
    constexpr int NCW = 32;
    constexpr int NT = 4;
    constexpr int NG = 2;
    const bool is_od = (blockIdx.y != 0);
    const ChainProb& p = is_od ? pod : pdt;
    const int row0 = blockIdx.x * BR;
    if (row0 >= p.M) return;

    __shared__ __half As[2][BR][AST];
    __shared__ __half Ws[2][NCOLS][AST];

    const int M = p.M;
    const int t = threadIdx.x;
    const int lane = t & 31;
    const int wid = t >> 5;
    const int warp_m = wid >> 2;
    const int warp_n = wid & 3;
    const int grp = lane >> 2;
    const int qid = lane & 3;
    const int lr = t >> 2;
    const int lk = (t & 3) * 8;
    const int grow = row0 + lr;
    const int wn = t >> 2;
    const int wk = (t & 3) * 8;
    const int lm_r = (lane & 7) + ((lane >> 3) & 1) * 8;
    const int lm_c = ((lane >> 4) & 1) * 8;

    // ---- generic helpers ----
    // stage a gmem X chunk + W chunk into buffer buf
    auto stageG = [&](int buf, const __half* Xp, int stride, int k0,
                      const __half* Wp, int wstride, int wk0) {
        uint4 pa = make_uint4(0, 0, 0, 0);
        if (grow < M) pa = *(const uint4*)(Xp + (size_t)grow * stride + k0 + lk);
        *(uint4*)&As[buf][lr][lk] = pa;
        *(uint4*)&Ws[buf][wn][wk] =
            *(const uint4*)(Wp + (size_t)wn * wstride + wk0 + wk);
    };
    // mma one KC chunk from buffer buf into acc[2][NT][4]
    auto mmaChunk = [&](int buf, float acc[2][NT][4]) {
#pragma unroll
        for (int ks = 0; ks < KC; ks += 16) {
            unsigned af[2][4];
#pragma unroll
            for (int mi = 0; mi < 2; mi++) {
                int r = warp_m * 32 + mi * 16;
                LDSM_X4(af[mi][0], af[mi][1], af[mi][2], af[mi][3],
                        smem_u32(&As[buf][r + lm_r][ks + lm_c]));
            }
            unsigned bf[NG][4];
#pragma unroll
            for (int g = 0; g < NG; g++) {
                int c = warp_n * NCW + g * 16;
                LDSM_X4(bf[g][0], bf[g][1], bf[g][2], bf[g][3],
                        smem_u32(&Ws[buf][c + lm_r][ks + lm_c]));
            }
#pragma unroll
            for (int g = 0; g < NG; g++)
#pragma unroll
                for (int half = 0; half < 2; half++)
#pragma unroll
                    for (int mi = 0; mi < 2; mi++)
                        MMA_F16(acc[mi][g * 2 + half], af[mi],
                                bf[g][half], bf[g][half + 2]);
        }
    };
    // restage register accumulator (bias+relu, cols of warp warp_n==sel) into As
    auto restageY = [&](int buf, int sel, float acc[2][NT][4], const float* bias) {
        if (warp_n == sel) {
#pragma unroll
            for (int mi = 0; mi < 2; mi++)
#pragma unroll
                for (int ni = 0; ni < NT; ni++) {
                    int cl = ni * 8 + 2 * qid;
                    float2 bv = *(const float2*)(bias + warp_n * 32 + cl);
                    float v0 = fmaxf(acc[mi][ni][0] + bv.x, 0.f);
                    float v1 = fmaxf(acc[mi][ni][1] + bv.y, 0.f);
                    float v2 = fmaxf(acc[mi][ni][2] + bv.x, 0.f);
                    float v3 = fmaxf(acc[mi][ni][3] + bv.y, 0.f);
                    __half2 h0 = __floats2half2_rn(v0, v1);
                    __half2 h1 = __floats2half2_rn(v2, v3);
                    int r = warp_m * 32 + mi * 16 + grp;
                    *(__half2*)&As[buf][r][cl] = h0;
                    *(__half2*)&As[buf][r + 8][cl] = h1;
                }
        }
    };

    float accY1[2][NT][4];
#pragma unroll
    for (int mi = 0; mi < 2; mi++)
#pragma unroll
        for (int ni = 0; ni < NT; ni++)
#pragma unroll
            for (int c = 0; c < 4; c++) accY1[mi][ni][c] = 0.f;

    if (!is_od) {
        // ---- dt stage 1: Y1 = acc3@W1 + d1@W2 (8 chunks gmem) ----
        const int n1 = p.K1a / KC, n2 = p.K1b / KC, nch = n1 + n2;
#pragma unroll 1
        for (int cc = 0; cc < nch; ++cc) {
            const int buf = cc & 1;
            __syncthreads();
            if (cc < n1) stageG(buf, p.A1, p.K1a, cc * KC, p.W1, p.K1a, cc * KC);
            else stageG(buf, p.B1, p.K1b, (cc - n1) * KC, p.W2, p.K1b, (cc - n1) * KC);
            __syncthreads();
            mmaChunk(buf, accY1);
        }
    } else {
        // ---- od stage 0: Y0 = acc2@W0a + xod@W0b (6 chunks gmem) ----
        float accY0[2][NT][4];
#pragma unroll
        for (int mi = 0; mi < 2; mi++)
#pragma unroll
            for (int ni = 0; ni < NT; ni++)
#pragma unroll
                for (int c = 0; c < 4; c++) accY0[mi][ni][c] = 0.f;
        const int n0a = p.K0a / KC, n0b = p.K0b / KC, nch0 = n0a + n0b;
#pragma unroll 1
        for (int cc = 0; cc < nch0; ++cc) {
            const int buf = cc & 1;
            __syncthreads();
            if (cc < n0a) stageG(buf, p.A0, p.K0a, cc * KC, p.W0a, p.K0a, cc * KC);
            else stageG(buf, p.B0, p.K0b, (cc - n0a) * KC, p.W0b, p.K0b, (cc - n0a) * KC);
            __syncthreads();
            mmaChunk(buf, accY0);
        }
        // ---- od stage 1: Y1 = acc2@W1 (4 gmem chunks) + Y0@W2 (4 reg chunks) ----
        const int n1 = p.K1a / KC;   // 4
#pragma unroll 1
        for (int cc = 0; cc < n1 + 4; ++cc) {
            const int buf = cc & 1;
            __syncthreads();
            if (cc < n1) {
                stageG(buf, p.A1, p.K1a, cc * KC, p.W1, p.K1a, cc * KC);
            } else {
                restageY(buf, cc - n1, accY0, p.bias0);
                *(uint4*)&Ws[buf][wn][wk] =
                    *(const uint4*)(p.W2 + (size_t)wn * 128 + (cc - n1) * KC + wk);
            }
            __syncthreads();
            mmaChunk(buf, accY1);
        }
    }

    // ---- stage 2: z = relu(Y1 + bias1) @ W3 + bias3, 4 chunks from registers ----
    float acc2[2][2][4];
#pragma unroll
    for (int mi = 0; mi < 2; mi++)
#pragma unroll
        for (int ni = 0; ni < 2; ni++)
#pragma unroll
            for (int c = 0; c < 4; c++) acc2[mi][ni][c] = 0.f;

#pragma unroll 1
    for (int cc2 = 0; cc2 < 4; ++cc2) {
        const int buf = cc2 & 1;
        __syncthreads();
        restageY(buf, cc2, accY1, p.bias1);
        {
            int wn2 = t >> 3;
            int wk2 = (t & 7) * 4;
            *(uint2*)&Ws[buf][wn2][wk2] =
                *(const uint2*)(p.W3 + (size_t)wn2 * 128 + cc2 * 32 + wk2);
        }
        __syncthreads();
#pragma unroll
        for (int ks = 0; ks < KC; ks += 16) {
            unsigned af2[2][4];
#pragma unroll
            for (int mi = 0; mi < 2; mi++) {
                int r = warp_m * 32 + mi * 16;
                LDSM_X4(af2[mi][0], af2[mi][1], af2[mi][2], af2[mi][3],
                        smem_u32(&As[buf][r + lm_r][ks + lm_c]));
            }
            unsigned bf2[4];
            LDSM_X4(bf2[0], bf2[1], bf2[2], bf2[3],
                    smem_u32(&Ws[buf][warp_n * 16 + lm_r][ks + lm_c]));
#pragma unroll
            for (int half = 0; half < 2; half++) {
                MMA_F16(acc2[0][half], af2[0], bf2[half], bf2[half + 2]);
                MMA_F16(acc2[1][half], af2[1], bf2[half], bf2[half + 2]);
            }
        }
    }

#pragma unroll
    for (int ni = 0; ni < 2; ni++) {
        int cb = warp_n * 16 + ni * 8 + 2 * qid;
        float2 bv = *(const float2*)(p.bias3 + cb);
#pragma unroll
        for (int mi = 0; mi < 2; mi++) {
            int r0 = row0 + warp_m * 32 + mi * 16 + grp;
            __half2 h0 = __floats2half2_rn(acc2[mi][ni][0] + bv.x, acc2[mi][ni][1] + bv.y);
            __half2 h1 = __floats2half2_rn(acc2[mi][ni][2] + bv.x, acc2[mi][ni][3] + bv.y);
            if (r0 < M)     *(__half2*)(p.Y2 + (size_t)r0 * 64 + cb) = h0;
            if (r0 + 8 < M) *(__half2*)(p.Y2 + (size_t)(r0 + 8) * 64 + cb) = h1;
        }
    }
}

// ---------------- fused edge decoder (fp16 mma + ldmatrix, KC=32) ---------------
__global__ __launch_bounds__(512, 2)
void dec_h(int M, const __half* __restrict__ zod, const __half* __restrict__ zdt,
           const int* __restrict__ esrc, const int* __restrict__ edst,
           const __half* __restrict__ Wt, const float* __restrict__ b1,
           const float* __restrict__ w2, const float* __restrict__ b2p,
           float* __restrict__ out) {
    constexpr int NC = 64;
    constexpr int BR = 128;
    constexpr int K = 128;
    constexpr int KC = 32;
    constexpr int AST = 40;
    constexpr int NCW = 16;
    constexpr int NT = 2;
    constexpr int NCH = K / KC;
    __shared__ __half As[2][BR][AST];
    __shared__ __half Ws[2][NC][AST];
    __shared__ float Red[BR][17];

    const int t = threadIdx.x;
    const int lane = t & 31;
    const int wid = t >> 5;
    const int warp_m = wid >> 2;
    const int warp_n = wid & 3;
    const int grp = lane >> 2;
    const int qid = lane & 3;
    const int row0 = blockIdx.x * BR;
    const int lr = t >> 2;
    const int lk = (t & 3) * 8;
    const int grow = row0 + lr;
    const int wn = t >> 3;
    const int wk = (t & 7) * 4;
    const int lm_r = (lane & 7) + ((lane >> 3) & 1) * 8;
    const int lm_c = ((lane >> 4) & 1) * 8;

    int si = 0, di = 0;
    if (grow < M) { si = __ldg(esrc + grow); di = __ldg(edst + grow); }

    uint4 pa = make_uint4(0, 0, 0, 0);
    uint2 pwv = make_uint2(0, 0);

    auto loadX = [&](int cc) {
        pa = make_uint4(0, 0, 0, 0);
        if (grow < M) {
            int k = cc * KC + lk;
            const __half* base = (k < 64) ? (zod + (size_t)si * 64 + k)
                                          : (zdt + (size_t)di * 64 + (k - 64));
            pa = *(const uint4*)base;
        }
    };
    auto loadW = [&](int cc) {
        pwv = *(const uint2*)(Wt + (size_t)wn * K + cc * KC + wk);
    };
    auto stage = [&](int buf) {
        *(uint4*)&As[buf][lr][lk] = pa;
        *(uint2*)&Ws[buf][wn][wk] = pwv;
    };

    float acc[2][NT][4];
#pragma unroll
    for (int mi = 0; mi < 2; mi++)
#pragma unroll
        for (int ni = 0; ni < NT; ni++)
#pragma unroll
            for (int c = 0; c < 4; c++) acc[mi][ni][c] = 0.f;

    loadX(0); loadW(0); stage(0);

#pragma unroll 1
    for (int cc = 0; cc < NCH; ++cc) {
        const int buf = cc & 1;
        __syncthreads();
        if (cc + 1 < NCH) { loadX(cc + 1); loadW(cc + 1); }
#pragma unroll
        for (int ks = 0; ks < KC; ks += 16) {
            unsigned af[2][4];
#pragma unroll
            for (int mi = 0; mi < 2; mi++) {
                int r = warp_m * 32 + mi * 16;
                LDSM_X4(af[mi][0], af[mi][1], af[mi][2], af[mi][3],
                        smem_u32(&As[buf][r + lm_r][ks + lm_c]));
            }
            unsigned bf[4];
            {
                int c = warp_n * NCW;
                LDSM_X4(bf[0], bf[1], bf[2], bf[3],
                        smem_u32(&Ws[buf][c + lm_r][ks + lm_c]));
            }
#pragma unroll
            for (int half = 0; half < 2; half++) {
                unsigned b0 = bf[half];
                unsigned b1 = bf[half + 2];
                MMA_F16(acc[0][half], af[0], b0, b1);
                MMA_F16(acc[1][half], af[1], b0, b1);
            }
        }
        if (cc + 1 < NCH) stage(buf ^ 1);
    }

    float p[2][2] = {{0.f, 0.f}, {0.f, 0.f}};
#pragma unroll
    for (int ni = 0; ni < NT; ni++) {
        int cb = warp_n * NCW + ni * 8 + 2 * qid;
        float2 bv = *(const float2*)(b1 + cb);
        float2 wv = *(const float2*)(w2 + cb);
#pragma unroll
        for (int mi = 0; mi < 2; mi++) {
            p[mi][0] += fmaxf(acc[mi][ni][0] + bv.x, 0.f) * wv.x
                      + fmaxf(acc[mi][ni][1] + bv.y, 0.f) * wv.y;
            p[mi][1] += fmaxf(acc[mi][ni][2] + bv.x, 0.f) * wv.x
                      + fmaxf(acc[mi][ni][3] + bv.y, 0.f) * wv.y;
        }
    }
    __syncthreads();
#pragma unroll
    for (int mi = 0; mi < 2; mi++) {
        Red[warp_m * 32 + mi * 16 + grp    ][warp_n * 4 + qid] = p[mi][0];
        Red[warp_m * 32 + mi * 16 + grp + 8][warp_n * 4 + qid] = p[mi][1];
    }
    __syncthreads();
    if (t < BR) {
        int r = row0 + t;
        if (r < M) {
            float s = 0.f;
#pragma unroll
            for (int j = 0; j < 16; j++) s += Red[t][j];
            out[r] = 1.f / (1.f + expf(-(s + b2p[0])));
        }
    }
}

// ---------------- host orchestration --------------------------------------------
extern "C" void kernel_launch(void* const* d_in, const int* in_sizes, int n_in,
                              void* d_out, int out_size) {
    const float* x_dt   = (const float*)d_in[0];
    const float* x_od   = (const float*)d_in[1];
    const int*   ei_dt  = (const int*)  d_in[2];
    const int*   rsrc   = (const int*)  d_in[3];
    const int*   rdst   = (const int*)  d_in[4];
    const int*   elsrc  = (const int*)  d_in[5];
    const int*   eldst  = (const int*)  d_in[6];
    const float* od1_wl = (const float*)d_in[7];
    const float* od1_wr = (const float*)d_in[8];
    const float* od1_b  = (const float*)d_in[9];
    const float* od2_wl = (const float*)d_in[10];
    const float* od2_wr = (const float*)d_in[11];
    const float* od2_b  = (const float*)d_in[12];
    const float* od3_wl = (const float*)d_in[13];
    const float* od3_wr = (const float*)d_in[14];
    const float* od3_b  = (const float*)d_in[15];
    const float* od_lw  = (const float*)d_in[16];
    const float* od_lb  = (const float*)d_in[17];
    const float* dt1_wl = (const float*)d_in[18];
    const float* dt1_wr = (const float*)d_in[19];
    const float* dt1_b  = (const float*)d_in[20];
    const float* dt2_wl = (const float*)d_in[21];
    const float* dt2_wr = (const float*)d_in[22];
    const float* dt2_b  = (const float*)d_in[23];
    const float* dt_lw  = (const float*)d_in[24];
    const float* dt_lb  = (const float*)d_in[25];
    const float* dec_w1 = (const float*)d_in[26];
    const float* dec_b1 = (const float*)d_in[27];
    const float* dec_w2 = (const float*)d_in[28];
    const float* dec_b2 = (const float*)d_in[29];
    float* out = (float*)d_out;

    const int E1 = in_sizes[2] / 2;
    const int E2 = in_sizes[3];
    const int EL = in_sizes[5];
    const int* r1 = ei_dt;
    const int* c1 = ei_dt + E1;

    __half *xdth, *xodh, *acc1, *acc2, *acc3, *h, *d1, *zodh, *zdth, *wh;
    int *deg1, *rp1, *fill1, *es1, *deg2, *rp2, *fill2, *es2, *part1, *part2, *scnt;
    cudaGetSymbolAddress((void**)&xdth, g_xdth);
    cudaGetSymbolAddress((void**)&xodh, g_xodh);
    cudaGetSymbolAddress((void**)&acc1, g_acc1);
    cudaGetSymbolAddress((void**)&acc2, g_acc2);
    cudaGetSymbolAddress((void**)&acc3, g_acc3);
    cudaGetSymbolAddress((void**)&h,   g_h);
    cudaGetSymbolAddress((void**)&d1,  g_d1);
    cudaGetSymbolAddress((void**)&zodh, g_zodh);
    cudaGetSymbolAddress((void**)&zdth, g_zdth);
    cudaGetSymbolAddress((void**)&wh,  g_wh);
    cudaGetSymbolAddress((void**)&deg1, g_deg1);
    cudaGetSymbolAddress((void**)&rp1, g_rp1);
    cudaGetSymbolAddress((void**)&fill1, g_fill1);
    cudaGetSymbolAddress((void**)&es1, g_es1);
    cudaGetSymbolAddress((void**)&deg2, g_deg2);
    cudaGetSymbolAddress((void**)&rp2, g_rp2);
    cudaGetSymbolAddress((void**)&fill2, g_fill2);
    cudaGetSymbolAddress((void**)&es2, g_es2);
    cudaGetSymbolAddress((void**)&part1, g_part1);
    cudaGetSymbolAddress((void**)&part2, g_part2);
    cudaGetSymbolAddress((void**)&scnt, g_scan_cnt);

    const int TB = 256;
    const int tiles1 = cdiv(NDT, TILE);
    const int tiles2 = cdiv(NOD, TILE);

    // ---- fused prep: weights transpose/convert + input convert + zeroing ----
    WTList L;
    const float* ws[13] = {od1_wl, od1_wr, dt1_wl, dt1_wr, od2_wl, od2_wr,
                           od3_wl, od3_wr, od_lw, dt2_wl, dt2_wr, dt_lw, dec_w1};
    int Ks[13] = {128, 128, 128, 128, 128, 64, 128, 128, 128, 128, 128, 128, 128};
    int Ns[13] = {128, 128, 128, 128, 128, 128, 128, 128, 64, 128, 128, 64, 64};
    int wt_tot = 0;
    for (int i = 0; i < 13; i++) {
        L.src[i] = ws[i]; L.K[i] = Ks[i]; L.N[i] = Ns[i];
        wt_tot += Ks[i] * Ns[i];
    }
    int prep_items = wt_tot + NDT * 32 + NOD * 16 + NDT / 4 + NOD / 4 + 1;
    k_prep<<<cdiv(prep_items, TB), TB>>>(L, wh, wt_tot, x_dt, xdth, x_od, xodh,
                                         deg1, deg2, scnt);
#define WT(i) (wh + (size_t)(i) * WSLOT)

    // ---- CSR build ----
    k_degree2<<<cdiv(E1 + E2, TB), TB>>>(c1, E1, deg1, rdst, E2, deg2);
    k_scan<<<tiles1 + tiles2, TB>>>(deg1, NDT, rp1, fill1, part1, tiles1,
                                    deg2, NOD, rp2, fill2, part2, tiles2, scnt);
    k_reorder2<<<cdiv(E1 + E2, TB), TB>>>(r1, c1, E1, fill1, es1,
                                          rsrc, rdst, E2, fill2, es2);

    // ---- pipeline ----
    k_aggh2<<<cdiv((long long)NDT * 32, TB), TB>>>(
        xdth, es1, rp1, acc1, NDT, nullptr, nullptr, nullptr, nullptr, 0);

    GemmProb ph  = {acc1, 128, xdth, 128, WT(0), WT(1), od1_b, h,  NDT, 1};
    GemmProb pd1 = {acc1, 128, xdth, 128, WT(2), WT(3), dt1_b, d1, NDT, 1};
    gemm_h<128, 128><<<dim3(cdiv(NDT, 128), 2), 256>>>(ph, pd1);

    k_aggh2<<<cdiv((long long)(NOD + NDT) * 32, TB), TB>>>(
        h, es2, rp2, acc2, NOD, d1, es1, rp1, acc3, NDT);

    // chained: dt 2-stage (y=0), od 3-stage (y=1, od2 fused in)
    ChainProb cdt = {nullptr, 0, nullptr, 0, nullptr, nullptr, nullptr,
                     acc3, 128, d1, 128, WT(9), WT(10), dt2_b,
                     WT(11), dt_lb, zdth, NDT};
    ChainProb cod = {acc2, 128, xodh, 64, WT(4), WT(5), od2_b,
                     acc2, 128, nullptr, 0, WT(6), WT(7), od3_b,
                     WT(8), od_lb, zodh, NOD};
    chain_h<<<dim3(cdiv(NDT, 128), 2), 512>>>(cdt, cod);

    dec_h<<<cdiv(EL, 128), 512>>>(EL, zodh, zdth, elsrc, eldst,
                                  WT(12), dec_b1, dec_w2, dec_b2, out);
}

// round 16
// speedup vs baseline: 1.0630x; 1.0616x over previous
#include <cuda_runtime.h>
#include <cuda_fp16.h>
#include <math.h>

#define NDT 30000
#define NOD 10000
#define WSLOT 16384
#define TILE 1024

static inline int cdiv(long long a, long long b) { return (int)((a + b - 1) / b); }

// ---------------- fp16 mma / ldmatrix helpers -----------------------------------
#define MMA_F16(d, a, b0, b1)                                              \
    asm volatile("mma.sync.aligned.m16n8k16.row.col.f32.f16.f16.f32 "      \
                 "{%0,%1,%2,%3}, {%4,%5,%6,%7}, {%8,%9}, {%0,%1,%2,%3};"   \
                 : "+f"((d)[0]), "+f"((d)[1]), "+f"((d)[2]), "+f"((d)[3])  \
                 : "r"((a)[0]), "r"((a)[1]), "r"((a)[2]), "r"((a)[3]),     \
                   "r"(b0), "r"(b1))

#define LDSM_X4(r0, r1, r2, r3, addr)                                      \
    asm volatile("ldmatrix.sync.aligned.m8n8.x4.shared.b16 "               \
                 "{%0,%1,%2,%3}, [%4];"                                    \
                 : "=r"(r0), "=r"(r1), "=r"(r2), "=r"(r3) : "r"(addr))

__device__ __forceinline__ unsigned smem_u32(const void* p) {
    return (unsigned)__cvta_generic_to_shared(p);
}

// ---------------- device scratch ------------------------------------------------
__device__ __half g_xdth[NDT * 128];
__device__ __half g_xodh[NOD * 64];
__device__ __half g_acc1[NDT * 128];
__device__ __half g_acc2[NOD * 128];
__device__ __half g_acc3[NDT * 128];
__device__ __half g_h [NDT * 128];
__device__ __half g_d1[NDT * 128];
__device__ __half g_od2[NOD * 128];
__device__ __half g_zodh[NOD * 64];
__device__ __half g_zdth[NDT * 64];
__device__ __half g_uod[NOD * 64];
__device__ __half g_udt[NDT * 64];
__device__ __half g_wh[14 * WSLOT];
// CSR scratch
__device__ int g_deg1[NDT];
__device__ int g_rp1[NDT + 1];
__device__ int g_fill1[NDT];
__device__ int g_es1[500000];
__device__ int g_deg2[NOD];
__device__ int g_rp2[NOD + 1];
__device__ int g_fill2[NOD];
__device__ int g_es2[300000];
__device__ int g_part1[64];
__device__ int g_part2[64];
__device__ int g_scan_cnt;

// ---------------- fused prep: weight transpose + input convert + zeroing --------
struct WTList {
    const float* src[14];
    int K[14];
    int N[14];
};
__global__ void k_prep(WTList L, __half* __restrict__ wdst, int wt_tot,
                       const float* __restrict__ x_dt, __half* __restrict__ xdh,
                       const float* __restrict__ x_od, __half* __restrict__ xoh,
                       int* __restrict__ deg1, int* __restrict__ deg2,
                       int* __restrict__ cnt) {
    int i = blockIdx.x * blockDim.x + threadIdx.x;
    if (i < wt_tot) {
        int s = 0, off = i;
        while (off >= L.K[s] * L.N[s]) { off -= L.K[s] * L.N[s]; s++; }
        int K = L.K[s];
        int n = off / K, k = off - n * K;
        wdst[(size_t)s * WSLOT + off] = __float2half(L.src[s][k * L.N[s] + n]);
        return;
    }
    i -= wt_tot;
    const int n1 = NDT * 128 / 4, n2 = NOD * 64 / 4;
    const int z1 = NDT / 4, z2 = NOD / 4;
    if (i < n1) {
        float4 v = *(const float4*)(x_dt + i * 4);
        __half2 h0 = __floats2half2_rn(v.x, v.y);
        __half2 h1 = __floats2half2_rn(v.z, v.w);
        *(uint2*)(xdh + i * 4) = make_uint2(*(unsigned*)&h0, *(unsigned*)&h1);
    } else if (i < n1 + n2) {
        int j = i - n1;
        float4 v = *(const float4*)(x_od + j * 4);
        __half2 h0 = __floats2half2_rn(v.x, v.y);
        __half2 h1 = __floats2half2_rn(v.z, v.w);
        *(uint2*)(xoh + j * 4) = make_uint2(*(unsigned*)&h0, *(unsigned*)&h1);
    } else if (i < n1 + n2 + z1) {
        ((int4*)deg1)[i - (n1 + n2)] = make_int4(0, 0, 0, 0);
    } else if (i < n1 + n2 + z1 + z2) {
        ((int4*)deg2)[i - (n1 + n2 + z1)] = make_int4(0, 0, 0, 0);
    } else if (i == n1 + n2 + z1 + z2) {
        *cnt = 0;
    }
}

// ---------------- CSR build ------------------------------------------------------
__global__ void k_degree2(const int* __restrict__ c1, int E1, int* __restrict__ deg1,
                          const int* __restrict__ rdst, int E2, int* __restrict__ deg2) {
    int i = blockIdx.x * blockDim.x + threadIdx.x;
    if (i < E1) atomicAdd(deg1 + __ldg(c1 + i), 1);
    else if (i < E1 + E2) atomicAdd(deg2 + __ldg(rdst + (i - E1)), 1);
}

__global__ void k_scan(const int* __restrict__ deg1, int n1, int* __restrict__ rp1,
                       int* __restrict__ fill1, int* __restrict__ part1, int tiles1,
                       const int* __restrict__ deg2, int n2, int* __restrict__ rp2,
                       int* __restrict__ fill2, int* __restrict__ part2, int tiles2,
                       int* __restrict__ cnt) {
    int b = blockIdx.x;
    const int* deg; int n; int* rp; int* fill; int* part; int tt, tiles;
    if (b < tiles1) { deg = deg1; n = n1; rp = rp1; fill = fill1; part = part1; tt = b; tiles = tiles1; }
    else { deg = deg2; n = n2; rp = rp2; fill = fill2; part = part2; tt = b - tiles1; tiles = tiles2; }
    __shared__ int wsum[8];
    __shared__ int s_off;
    int t = threadIdx.x, lane = t & 31, w = t >> 5;
    int base = tt * TILE + t * 4;
    int d[4]; int tot = 0;
#pragma unroll
    for (int j = 0; j < 4; j++) { d[j] = (base + j < n) ? deg[base + j] : 0; tot += d[j]; }
    int inc = tot;
#pragma unroll
    for (int o = 1; o < 32; o <<= 1) {
        int u = __shfl_up_sync(0xffffffffu, inc, o);
        if (lane >= o) inc += u;
    }
    if (lane == 31) wsum[w] = inc;
    __syncthreads();
    if (t == 0) {
        int s = 0;
#pragma unroll
        for (int j = 0; j < 8; j++) s += wsum[j];
        part[tt] = s;
        __threadfence();
        atomicAdd(cnt, 1);
        while (atomicAdd(cnt, 0) < tiles1 + tiles2) {}
        __threadfence();
    }
    __syncthreads();
    if (t < 32) {
        int v = (t < tt) ? atomicAdd(part + t, 0) : 0;
#pragma unroll
        for (int o = 16; o; o >>= 1) v += __shfl_xor_sync(0xffffffffu, v, o);
        if (t == 0) s_off = v;
    }
    __syncthreads();
    int woff = 0;
#pragma unroll
    for (int j = 0; j < 8; j++) if (j < w) woff += wsum[j];
    int run = s_off + woff + inc - tot;
#pragma unroll
    for (int j = 0; j < 4; j++) {
        if (base + j < n) { rp[base + j] = run; fill[base + j] = run; run += d[j]; }
    }
    if (tt == tiles - 1 && t == blockDim.x - 1) rp[n] = run;
}

__global__ void k_reorder2(const int* __restrict__ s1, const int* __restrict__ t1, int E1,
                           int* __restrict__ f1, int* __restrict__ e1,
                           const int* __restrict__ s2, const int* __restrict__ t2, int E2,
                           int* __restrict__ f2, int* __restrict__ e2) {
    int i = blockIdx.x * blockDim.x + threadIdx.x;
    if (i < E1) {
        int d = __ldg(t1 + i);
        int pos = atomicAdd(f1 + d, 1);
        e1[pos] = __ldg(s1 + i);
    } else if (i < E1 + E2) {
        int j = i - E1;
        int d = __ldg(t2 + j);
        int pos = atomicAdd(f2 + d, 1);
        e2[pos] = __ldg(s2 + j);
    }
}

// ---------------- mean aggregation: warp per dst, 4 edges in flight -------------
__global__ __launch_bounds__(256)
void k_aggh2(const __half* __restrict__ X1, const int* __restrict__ es1,
             const int* __restrict__ rp1, __half* __restrict__ acc1, int n1,
             const __half* __restrict__ X2, const int* __restrict__ es2,
             const int* __restrict__ rp2, __half* __restrict__ acc2, int n2) {
    int w = (blockIdx.x * blockDim.x + threadIdx.x) >> 5;
    const __half* X; const int* es; const int* rowptr; __half* acc;
    if (w < n1) { X = X1; es = es1; rowptr = rp1; acc = acc1; }
    else if (w < n1 + n2) { X = X2; es = es2; rowptr = rp2; acc = acc2; w -= n1; }
    else return;
    int lane = threadIdx.x & 31;
    int grp4 = lane >> 3;
    int sub = lane & 7;
    int beg = __ldg(rowptr + w);
    int end = __ldg(rowptr + w + 1);
    float s[16];
#pragma unroll
    for (int k = 0; k < 16; k++) s[k] = 0.f;
    for (int base = beg; base < end; base += 32) {
        int p = 0;
        if (base + lane < end) p = __ldg(es + base + lane);
        int cnt = min(32, end - base);
        for (int j = 0; j < cnt; j += 4) {
            int e = j + grp4;
            int sr = __shfl_sync(0xffffffffu, p, e);
            if (e < cnt) {
                const uint4* row = (const uint4*)(X + (size_t)sr * 128 + sub * 16);
                uint4 v0 = __ldg(row);
                uint4 v1 = __ldg(row + 1);
                unsigned vv[8] = {v0.x, v0.y, v0.z, v0.w, v1.x, v1.y, v1.z, v1.w};
#pragma unroll
                for (int k = 0; k < 8; k++) {
                    float2 f = __half22float2(*(__half2*)&vv[k]);
                    s[2 * k] += f.x;
                    s[2 * k + 1] += f.y;
                }
            }
        }
    }
#pragma unroll
    for (int k = 0; k < 16; k++) {
        s[k] += __shfl_xor_sync(0xffffffffu, s[k], 8);
        s[k] += __shfl_xor_sync(0xffffffffu, s[k], 16);
    }
    if (grp4 == 0) {
        float inv = 1.f / fmaxf((float)(end - beg), 1.f);
        unsigned o[8];
#pragma unroll
        for (int k = 0; k < 8; k++) {
            __half2 hv = __floats2half2_rn(s[2 * k] * inv, s[2 * k + 1] * inv);
            o[k] = *(unsigned*)&hv;
        }
        uint4* dst = (uint4*)(acc + (size_t)w * 128 + sub * 16);
        dst[0] = make_uint4(o[0], o[1], o[2], o[3]);
        dst[1] = make_uint4(o[4], o[5], o[6], o[7]);
    }
}

// ---------------- generic 2-problem fp16 GEMM (256 thr, 2m x 4n warps) ----------
struct GemmProb {
    const __half* A; int K1;
    const __half* B; int K2;
    const __half* W1; const __half* W2;   // pre-transposed [N][K] f16
    const float* bias;
    __half* Y;
    int M;
    int relu;
};

template <int NCOLS, int BR>
__global__ __launch_bounds__(256, 2)
void gemm_h(GemmProb p0, GemmProb p1) {
    constexpr int KC = 32;
    constexpr int AST = 40;
    constexpr int MI = BR / 32;
    constexpr int NCW = NCOLS / 4;
    constexpr int NT = NCW / 8;
    constexpr int NG = (NT + 1) / 2;
    constexpr int APT = BR * KC / 256;
    constexpr int WPT = NCOLS * KC / 256;
    const GemmProb& p = blockIdx.y ? p1 : p0;
    const int row0 = blockIdx.x * BR;
    if (row0 >= p.M) return;

    __shared__ __half As[2][BR][AST];
    __shared__ __half Ws[2][NCOLS][AST];

    const int M = p.M;
    const int K1 = p.K1, K2 = p.K2;
    const __half* A = p.A;
    const __half* B = p.B;

    const int t = threadIdx.x;
    const int lane = t & 31;
    const int wid = t >> 5;
    const int warp_m = wid >> 2;
    const int warp_n = wid & 3;
    const int grp = lane >> 2;
    const int qid = lane & 3;
    const int lr = (BR == 128) ? (t >> 1) : (t >> 2);
    const int lk = (BR == 128) ? ((t & 1) * 16) : ((t & 3) * 8);
    const int grow = row0 + lr;
    const int wn = (NCOLS == 128) ? (t >> 1) : (t >> 2);
    const int wk = (NCOLS == 128) ? ((t & 1) * 16) : ((t & 3) * 8);
    const int lm_r = (lane & 7) + ((lane >> 3) & 1) * 8;
    const int lm_c = ((lane >> 4) & 1) * 8;

    const int n1 = K1 / KC;
    const int n2 = (B != nullptr) ? (K2 / KC) : 0;
    const int nch = n1 + n2;

    uint4 pa0 = make_uint4(0, 0, 0, 0), pa1 = make_uint4(0, 0, 0, 0);
    uint4 pw0 = make_uint4(0, 0, 0, 0), pw1 = make_uint4(0, 0, 0, 0);

    auto loadX = [&](int cc) {
        const __half* Xp; int stride, k0;
        if (cc < n1) { Xp = A; stride = K1; k0 = cc * KC; }
        else         { Xp = B; stride = K2; k0 = (cc - n1) * KC; }
        pa0 = make_uint4(0, 0, 0, 0); pa1 = pa0;
        if (grow < M) {
            const __half* base = Xp + (size_t)grow * stride + k0 + lk;
            pa0 = *(const uint4*)base;
            if (APT == 16) pa1 = *(const uint4*)(base + 8);
        }
    };
    auto loadW = [&](int cc) {
        const __half* Wp; int stride, k0;
        if (cc < n1) { Wp = p.W1; stride = K1; k0 = cc * KC; }
        else         { Wp = p.W2; stride = K2; k0 = (cc - n1) * KC; }
        const __half* base = Wp + (size_t)wn * stride + k0 + wk;
        pw0 = *(const uint4*)base;
        if (WPT == 16) pw1 = *(const uint4*)(base + 8);
    };
    auto stage = [&](int buf) {
        *(uint4*)&As[buf][lr][lk] = pa0;
        if (APT == 16) *(uint4*)&As[buf][lr][lk + 8] = pa1;
        *(uint4*)&Ws[buf][wn][wk] = pw0;
        if (WPT == 16) *(uint4*)&Ws[buf][wn][wk + 8] = pw1;
    };

    float acc[MI][NT][4];
#pragma unroll
    for (int mi = 0; mi < MI; mi++)
#pragma unroll
        for (int ni = 0; ni < NT; ni++)
#pragma unroll
            for (int c = 0; c < 4; c++) acc[mi][ni][c] = 0.f;

    loadX(0); loadW(0); stage(0);

    for (int cc = 0; cc < nch; ++cc) {
        const int buf = cc & 1;
        __syncthreads();
        if (cc + 1 < nch) { loadX(cc + 1); loadW(cc + 1); }
#pragma unroll
        for (int ks = 0; ks < KC; ks += 16) {
            unsigned bf[NG][4];
#pragma unroll
            for (int g = 0; g < NG; g++) {
                int c = warp_n * NCW + g * 16;
                LDSM_X4(bf[g][0], bf[g][1], bf[g][2], bf[g][3],
                        smem_u32(&Ws[buf][c + lm_r][ks + lm_c]));
            }
#pragma unroll
            for (int mi = 0; mi < MI; mi++) {
                unsigned af[4];
                int r = warp_m * (16 * MI) + mi * 16;
                LDSM_X4(af[0], af[1], af[2], af[3],
                        smem_u32(&As[buf][r + lm_r][ks + lm_c]));
#pragma unroll
                for (int g = 0; g < NG; g++) {
#pragma unroll
                    for (int half = 0; half < 2; half++) {
                        int ni = g * 2 + half;
                        if (ni < NT)
                            MMA_F16(acc[mi][ni], af, bf[g][half], bf[g][half + 2]);
                    }
                }
            }
        }
        if (cc + 1 < nch) stage(buf ^ 1);
    }

#pragma unroll
    for (int ni = 0; ni < NT; ni++) {
        int cb = warp_n * NCW + ni * 8 + 2 * qid;
        float2 bv = make_float2(0.f, 0.f);
        if (p.bias != nullptr) bv = *(const float2*)(p.bias + cb);
#pragma unroll
        for (int mi = 0; mi < MI; mi++) {
            int r0 = row0 + warp_m * (16 * MI) + mi * 16 + grp;
            float v0 = acc[mi][ni][0] + bv.x;
            float v1 = acc[mi][ni][1] + bv.y;
            float v2 = acc[mi][ni][2] + bv.x;
            float v3 = acc[mi][ni][3] + bv.y;
            if (p.relu) {
                v0 = fmaxf(v0, 0.f); v1 = fmaxf(v1, 0.f);
                v2 = fmaxf(v2, 0.f); v3 = fmaxf(v3, 0.f);
            }
            __half2 h0 = __floats2half2_rn(v0, v1);
            __half2 h1 = __floats2half2_rn(v2, v3);
            if (r0 < M)     *(__half2*)(p.Y + (size_t)r0 * NCOLS + cb) = h0;
            if (r0 + 8 < M) *(__half2*)(p.Y + (size_t)(r0 + 8) * NCOLS + cb) = h1;
        }
    }
}

// ---------------- chained GEMM (R13): Y2 = (relu(A@W1 + B@W2 + b)) @ W3 + b3 ----
struct ChainProb {
    const __half* A; int K1;
    const __half* B; int K2;
    const __half* W1; const __half* W2;
    const float* bias;
    const __half* W3;
    const float* bias3;
    __half* Y2;
    int M;
};

__global__ __launch_bounds__(512, 1)
void chain_h(ChainProb p0, ChainProb p1) {
    constexpr int KC = 32;
    constexpr int AST = 40;
    constexpr int BR = 128;
    constexpr int NCOLS = 128;
    constexpr int NCW = 32;
    constexpr int NT = 4;
    constexpr int NG = 2;
    const ChainProb& p = blockIdx.y ? p1 : p0;
    const int row0 = blockIdx.x * BR;
    if (row0 >= p.M) return;

    __shared__ __half As[2][BR][AST];
    __shared__ __half Ws[2][NCOLS][AST];

    const int M = p.M;
    const int K1 = p.K1, K2 = p.K2;

    const int t = threadIdx.x;
    const int lane = t & 31;
    const int wid = t >> 5;
    const int warp_m = wid >> 2;
    const int warp_n = wid & 3;
    const int grp = lane >> 2;
    const int qid = lane & 3;
    const int lr = t >> 2;
    const int lk = (t & 3) * 8;
    const int grow = row0 + lr;
    const int wn = t >> 2;
    const int wk = (t & 3) * 8;
    const int lm_r = (lane & 7) + ((lane >> 3) & 1) * 8;
    const int lm_c = ((lane >> 4) & 1) * 8;

    const int n1 = K1 / KC;
    const int n2 = K2 / KC;
    const int nch = n1 + n2;

    uint4 pa = make_uint4(0, 0, 0, 0), pw = make_uint4(0, 0, 0, 0);

    auto loadX = [&](int cc) {
        const __half* Xp; int stride, k0;
        if (cc < n1) { Xp = p.A; stride = K1; k0 = cc * KC; }
        else         { Xp = p.B; stride = K2; k0 = (cc - n1) * KC; }
        pa = make_uint4(0, 0, 0, 0);
        if (grow < M) pa = *(const uint4*)(Xp + (size_t)grow * stride + k0 + lk);
    };
    auto loadW = [&](int cc) {
        const __half* Wp; int stride, k0;
        if (cc < n1) { Wp = p.W1; stride = K1; k0 = cc * KC; }
        else         { Wp = p.W2; stride = K2; k0 = (cc - n1) * KC; }
        pw = *(const uint4*)(Wp + (size_t)wn * stride + k0 + wk);
    };
    auto stage = [&](int buf) {
        *(uint4*)&As[buf][lr][lk] = pa;
        *(uint4*)&Ws[buf][wn][wk] = pw;
    };

    float acc[2][NT][4];
#pragma unroll
    for (int mi = 0; mi < 2; mi++)
#pragma unroll
        for (int ni = 0; ni < NT; ni++)
#pragma unroll
            for (int c = 0; c < 4; c++) acc[mi][ni][c] = 0.f;

    loadX(0); loadW(0); stage(0);

    for (int cc = 0; cc < nch; ++cc) {
        const int buf = cc & 1;
        __syncthreads();
        if (cc + 1 < nch) { loadX(cc + 1); loadW(cc + 1); }
#pragma unroll
        for (int ks = 0; ks < KC; ks += 16) {
            unsigned af[2][4];
#pragma unroll
            for (int mi = 0; mi < 2; mi++) {
                int r = warp_m * 32 + mi * 16;
                LDSM_X4(af[mi][0], af[mi][1], af[mi][2], af[mi][3],
                        smem_u32(&As[buf][r + lm_r][ks + lm_c]));
            }
            unsigned bf[NG][4];
#pragma unroll
            for (int g = 0; g < NG; g++) {
                int c = warp_n * NCW + g * 16;
                LDSM_X4(bf[g][0], bf[g][1], bf[g][2], bf[g][3],
                        smem_u32(&Ws[buf][c + lm_r][ks + lm_c]));
            }
#pragma unroll
            for (int g = 0; g < NG; g++) {
#pragma unroll
                for (int half = 0; half < 2; half++) {
#pragma unroll
                    for (int mi = 0; mi < 2; mi++)
                        MMA_F16(acc[mi][g * 2 + half], af[mi], bf[g][half], bf[g][half + 2]);
                }
            }
        }
        if (cc + 1 < nch) stage(buf ^ 1);
    }

    float acc2[2][2][4];
#pragma unroll
    for (int mi = 0; mi < 2; mi++)
#pragma unroll
        for (int ni = 0; ni < 2; ni++)
#pragma unroll
            for (int c = 0; c < 4; c++) acc2[mi][ni][c] = 0.f;

#pragma unroll 1
    for (int cc2 = 0; cc2 < 4; ++cc2) {
        const int buf = cc2 & 1;
        __syncthreads();
        if (warp_n == cc2) {
#pragma unroll
            for (int mi = 0; mi < 2; mi++)
#pragma unroll
                for (int ni = 0; ni < NT; ni++) {
                    int cl = ni * 8 + 2 * qid;
                    float2 bv = *(const float2*)(p.bias + warp_n * 32 + cl);
                    float v0 = fmaxf(acc[mi][ni][0] + bv.x, 0.f);
                    float v1 = fmaxf(acc[mi][ni][1] + bv.y, 0.f);
                    float v2 = fmaxf(acc[mi][ni][2] + bv.x, 0.f);
                    float v3 = fmaxf(acc[mi][ni][3] + bv.y, 0.f);
                    __half2 h0 = __floats2half2_rn(v0, v1);
                    __half2 h1 = __floats2half2_rn(v2, v3);
                    int r = warp_m * 32 + mi * 16 + grp;
                    *(__half2*)&As[buf][r][cl] = h0;
                    *(__half2*)&As[buf][r + 8][cl] = h1;
                }
        }
        {
            int wn2 = t >> 3;
            int wk2 = (t & 7) * 4;
            *(uint2*)&Ws[buf][wn2][wk2] =
                *(const uint2*)(p.W3 + (size_t)wn2 * 128 + cc2 * 32 + wk2);
        }
        __syncthreads();
#pragma unroll
        for (int ks = 0; ks < KC; ks += 16) {
            unsigned af2[2][4];
#pragma unroll
            for (int mi = 0; mi < 2; mi++) {
                int r = warp_m * 32 + mi * 16;
                LDSM_X4(af2[mi][0], af2[mi][1], af2[mi][2], af2[mi][3],
                        smem_u32(&As[buf][r + lm_r][ks + lm_c]));
            }
            unsigned bf2[4];
            LDSM_X4(bf2[0], bf2[1], bf2[2], bf2[3],
                    smem_u32(&Ws[buf][warp_n * 16 + lm_r][ks + lm_c]));
#pragma unroll
            for (int half = 0; half < 2; half++) {
                MMA_F16(acc2[0][half], af2[0], bf2[half], bf2[half + 2]);
                MMA_F16(acc2[1][half], af2[1], bf2[half], bf2[half + 2]);
            }
        }
    }

#pragma unroll
    for (int ni = 0; ni < 2; ni++) {
        int cb = warp_n * 16 + ni * 8 + 2 * qid;
        float2 bv = *(const float2*)(p.bias3 + cb);
#pragma unroll
        for (int mi = 0; mi < 2; mi++) {
            int r0 = row0 + warp_m * 32 + mi * 16 + grp;
            __half2 h0 = __floats2half2_rn(acc2[mi][ni][0] + bv.x, acc2[mi][ni][1] + bv.y);
            __half2 h1 = __floats2half2_rn(acc2[mi][ni][2] + bv.x, acc2[mi][ni][3] + bv.y);
            if (r0 < M)     *(__half2*)(p.Y2 + (size_t)r0 * 64 + cb) = h0;
            if (r0 + 8 < M) *(__half2*)(p.Y2 + (size_t)(r0 + 8) * 64 + cb) = h1;
        }
    }
}

// ---------------- decomposed decoder: per-edge elementwise ----------------------
// out[e] = sigmoid( relu(Uod[esrc[e]] + Udt[edst[e]]) . w2 + b2 )
// Uod already contains b1. 8 lanes per edge, 8 cols each.
__global__ __launch_bounds__(256)
void k_dec(int E, const __half* __restrict__ Uod, const __half* __restrict__ Udt,
           const int* __restrict__ esrc, const int* __restrict__ edst,
           const float* __restrict__ w2, const float* __restrict__ b2p,
           float* __restrict__ out) {
    int gid = blockIdx.x * blockDim.x + threadIdx.x;
    int e = gid >> 3;
    if (e >= E) return;
    int sub = gid & 7;
    int si = __ldg(esrc + e);
    int di = __ldg(edst + e);
    uint4 a = *(const uint4*)(Uod + (size_t)si * 64 + sub * 8);
    uint4 b = *(const uint4*)(Udt + (size_t)di * 64 + sub * 8);
    unsigned av[4] = {a.x, a.y, a.z, a.w};
    unsigned bv[4] = {b.x, b.y, b.z, b.w};
    const float* wv = w2 + sub * 8;
    float p = 0.f;
#pragma unroll
    for (int k = 0; k < 4; k++) {
        float2 fa = __half22float2(*(__half2*)&av[k]);
        float2 fb = __half22float2(*(__half2*)&bv[k]);
        p += fmaxf(fa.x + fb.x, 0.f) * __ldg(wv + 2 * k)
           + fmaxf(fa.y + fb.y, 0.f) * __ldg(wv + 2 * k + 1);
    }
    p += __shfl_xor_sync(0xffffffffu, p, 1);
    p += __shfl_xor_sync(0xffffffffu, p, 2);
    p += __shfl_xor_sync(0xffffffffu, p, 4);
    if (sub == 0) out[e] = 1.f / (1.f + expf(-(p + b2p[0])));
}

// ---------------- host orchestration --------------------------------------------
extern "C" void kernel_launch(void* const* d_in, const int* in_sizes, int n_in,
                              void* d_out, int out_size) {
    const float* x_dt   = (const float*)d_in[0];
    const float* x_od   = (const float*)d_in[1];
    const int*   ei_dt  = (const int*)  d_in[2];
    const int*   rsrc   = (const int*)  d_in[3];
    const int*   rdst   = (const int*)  d_in[4];
    const int*   elsrc  = (const int*)  d_in[5];
    const int*   eldst  = (const int*)  d_in[6];
    const float* od1_wl = (const float*)d_in[7];
    const float* od1_wr = (const float*)d_in[8];
    const float* od1_b  = (const float*)d_in[9];
    const float* od2_wl = (const float*)d_in[10];
    const float* od2_wr = (const float*)d_in[11];
    const float* od2_b  = (const float*)d_in[12];
    const float* od3_wl = (const float*)d_in[13];
    const float* od3_wr = (const float*)d_in[14];
    const float* od3_b  = (const float*)d_in[15];
    const float* od_lw  = (const float*)d_in[16];
    const float* od_lb  = (const float*)d_in[17];
    const float* dt1_wl = (const float*)d_in[18];
    const float* dt1_wr = (const float*)d_in[19];
    const float* dt1_b  = (const float*)d_in[20];
    const float* dt2_wl = (const float*)d_in[21];
    const float* dt2_wr = (const float*)d_in[22];
    const float* dt2_b  = (const float*)d_in[23];
    const float* dt_lw  = (const float*)d_in[24];
    const float* dt_lb  = (const float*)d_in[25];
    const float* dec_w1 = (const float*)d_in[26];
    const float* dec_b1 = (const float*)d_in[27];
    const float* dec_w2 = (const float*)d_in[28];
    const float* dec_b2 = (const float*)d_in[29];
    float* out = (float*)d_out;

    const int E1 = in_sizes[2] / 2;
    const int E2 = in_sizes[3];
    const int EL = in_sizes[5];
    const int* r1 = ei_dt;
    const int* c1 = ei_dt + E1;

    __half *xdth, *xodh, *acc1, *acc2, *acc3, *h, *d1, *od2b, *zodh, *zdth;
    __half *uod, *udt, *wh;
    int *deg1, *rp1, *fill1, *es1, *deg2, *rp2, *fill2, *es2, *part1, *part2, *scnt;
    cudaGetSymbolAddress((void**)&xdth, g_xdth);
    cudaGetSymbolAddress((void**)&xodh, g_xodh);
    cudaGetSymbolAddress((void**)&acc1, g_acc1);
    cudaGetSymbolAddress((void**)&acc2, g_acc2);
    cudaGetSymbolAddress((void**)&acc3, g_acc3);
    cudaGetSymbolAddress((void**)&h,   g_h);
    cudaGetSymbolAddress((void**)&d1,  g_d1);
    cudaGetSymbolAddress((void**)&od2b, g_od2);
    cudaGetSymbolAddress((void**)&zodh, g_zodh);
    cudaGetSymbolAddress((void**)&zdth, g_zdth);
    cudaGetSymbolAddress((void**)&uod, g_uod);
    cudaGetSymbolAddress((void**)&udt, g_udt);
    cudaGetSymbolAddress((void**)&wh,  g_wh);
    cudaGetSymbolAddress((void**)&deg1, g_deg1);
    cudaGetSymbolAddress((void**)&rp1, g_rp1);
    cudaGetSymbolAddress((void**)&fill1, g_fill1);
    cudaGetSymbolAddress((void**)&es1, g_es1);
    cudaGetSymbolAddress((void**)&deg2, g_deg2);
    cudaGetSymbolAddress((void**)&rp2, g_rp2);
    cudaGetSymbolAddress((void**)&fill2, g_fill2);
    cudaGetSymbolAddress((void**)&es2, g_es2);
    cudaGetSymbolAddress((void**)&part1, g_part1);
    cudaGetSymbolAddress((void**)&part2, g_part2);
    cudaGetSymbolAddress((void**)&scnt, g_scan_cnt);

    const int TB = 256;
    const int tiles1 = cdiv(NDT, TILE);
    const int tiles2 = cdiv(NOD, TILE);

    // ---- fused prep: weights transpose/convert + input convert + zeroing ----
    // slots 12/13: dec_w1 split into top (rows 0..63) and bottom (rows 64..127),
    // each transposed to [64][64].
    WTList L;
    const float* ws[14] = {od1_wl, od1_wr, dt1_wl, dt1_wr, od2_wl, od2_wr,
                           od3_wl, od3_wr, od_lw, dt2_wl, dt2_wr, dt_lw,
                           dec_w1, dec_w1 + 64 * 64};
    int Ks[14] = {128, 128, 128, 128, 128, 64, 128, 128, 128, 128, 128, 128, 64, 64};
    int Ns[14] = {128, 128, 128, 128, 128, 128, 128, 128, 64, 128, 128, 64, 64, 64};
    int wt_tot = 0;
    for (int i = 0; i < 14; i++) {
        L.src[i] = ws[i]; L.K[i] = Ks[i]; L.N[i] = Ns[i];
        wt_tot += Ks[i] * Ns[i];
    }
    int prep_items = wt_tot + NDT * 32 + NOD * 16 + NDT / 4 + NOD / 4 + 1;
    k_prep<<<cdiv(prep_items, TB), TB>>>(L, wh, wt_tot, x_dt, xdth, x_od, xodh,
                                         deg1, deg2, scnt);
#define WT(i) (wh + (size_t)(i) * WSLOT)

    // ---- CSR build ----
    k_degree2<<<cdiv(E1 + E2, TB), TB>>>(c1, E1, deg1, rdst, E2, deg2);
    k_scan<<<tiles1 + tiles2, TB>>>(deg1, NDT, rp1, fill1, part1, tiles1,
                                    deg2, NOD, rp2, fill2, part2, tiles2, scnt);
    k_reorder2<<<cdiv(E1 + E2, TB), TB>>>(r1, c1, E1, fill1, es1,
                                          rsrc, rdst, E2, fill2, es2);

    // ---- pipeline ----
    k_aggh2<<<cdiv((long long)NDT * 32, TB), TB>>>(
        xdth, es1, rp1, acc1, NDT, nullptr, nullptr, nullptr, nullptr, 0);

    GemmProb ph  = {acc1, 128, xdth, 128, WT(0), WT(1), od1_b, h,  NDT, 1};
    GemmProb pd1 = {acc1, 128, xdth, 128, WT(2), WT(3), dt1_b, d1, NDT, 1};
    gemm_h<128, 128><<<dim3(cdiv(NDT, 128), 2), 256>>>(ph, pd1);

    k_aggh2<<<cdiv((long long)(NOD + NDT) * 32, TB), TB>>>(
        h, es2, rp2, acc2, NOD, d1, es1, rp1, acc3, NDT);

    GemmProb pod2 = {acc2, 128, xodh, 64, WT(4), WT(5), od2_b, od2b, NOD, 1};
    gemm_h<128, 64><<<dim3(cdiv(NOD, 64), 1), 256>>>(pod2, pod2);

    ChainProb cod = {acc2, 128, od2b, 128, WT(6), WT(7), od3_b, WT(8), od_lb, zodh, NOD};
    ChainProb cdt = {acc3, 128, d1, 128, WT(9), WT(10), dt2_b, WT(11), dt_lb, zdth, NDT};
    chain_h<<<dim3(cdiv(NDT, 128), 2), 512>>>(cdt, cod);

    // decoder node-factor GEMMs: Uod = zod@W1_top + b1 ; Udt = zdt@W1_bot
    GemmProb pUod = {zodh, 64, nullptr, 0, WT(12), nullptr, dec_b1, uod, NOD, 0};
    GemmProb pUdt = {zdth, 64, nullptr, 0, WT(13), nullptr, nullptr, udt, NDT, 0};
    gemm_h<64, 128><<<dim3(cdiv(NDT, 128), 2), 256>>>(pUod, pUdt);

    // per-edge elementwise decoder
    k_dec<<<cdiv((long long)EL * 8, TB), TB>>>(EL, uod, udt, elsrc, eldst,
                                               dec_w2, dec_b2, out);
}